// round 1
// baseline (speedup 1.0000x reference)
#include <cuda_runtime.h>
#include <cstdint>
#include <cmath>

// Problem constants
// B=4, C=256, P=1024, T=64, H=8, D=32, DT = D*T = 2048
// SCALE = sqrt(D*T) = sqrt(2048)

#define NB 4
#define NC 256
#define NP 1024
#define NT 64
#define NH 8
#define ND 32
#define NDT 2048          // D*T
#define NPT 65536         // P*T

// Scratch buffers (allocation-free rule: __device__ globals)
__device__ float g_kbuf[(size_t)NB * NH * NP * NDT];   // [b][h][p][d*T+t]
__device__ float g_qbuf[(size_t)NB * NH * NP * NDT];
__device__ float g_vbuf[(size_t)NB * NH * NP * NDT];
__device__ float g_ebuf[(size_t)NB * NH * NP * NP];    // [z][p][q] energy -> attn (in place)

// ---------------------------------------------------------------------------
// Shared GEMM micro-kernel pieces: 128x128 tile, BK=16, 256 threads, 8x8/thread
// ---------------------------------------------------------------------------
#define BK 16
#define SPAD 132   // 128 + 4 padding (132*4B = 528B rows, 16B aligned)

// Load a 128(m) x 16(k) tile from a k-contiguous (row-major, ld = Kdim) matrix,
// transposing into S[k][m]. A must be pre-offset to tile row 0 (A += m0*lda).
__device__ __forceinline__ void load_tileT(float (*S)[SPAD], const float* __restrict__ A,
                                           int lda, int k0, int lt) {
    int row = lt >> 2;              // 0..63
    int c4  = (lt & 3) * 4;         // 0,4,8,12
#pragma unroll
    for (int r = 0; r < 2; ++r) {
        int m = row + r * 64;
        float4 v = *(const float4*)(A + (size_t)m * lda + k0 + c4);
        S[c4 + 0][m] = v.x;
        S[c4 + 1][m] = v.y;
        S[c4 + 2][m] = v.z;
        S[c4 + 3][m] = v.w;
    }
}

// Load a 16(k) x 128(n) tile from an n-contiguous (row-major, ld = N) matrix
// directly into S[k][n]. B must be pre-offset to tile col 0 (B += n0).
__device__ __forceinline__ void load_tileD(float (*S)[SPAD], const float* __restrict__ Bm,
                                           int ldb, int k0, int lt) {
    int kr = lt >> 5;               // 0..7
    int c4 = (lt & 31) * 4;         // 0..124
#pragma unroll
    for (int r = 0; r < 2; ++r) {
        int k = kr + r * 8;
        float4 v = *(const float4*)(Bm + (size_t)(k0 + k) * ldb + c4);
        *(float4*)&S[k][c4] = v;
    }
}

__device__ __forceinline__ void mm_step(const float (*As)[SPAD], const float (*Bs)[SPAD],
                                        float acc[8][8], int ty, int tx) {
#pragma unroll
    for (int kk = 0; kk < BK; ++kk) {
        float a[8], bb[8];
        *(float4*)&a[0]  = *(const float4*)&As[kk][ty * 8];
        *(float4*)&a[4]  = *(const float4*)&As[kk][ty * 8 + 4];
        *(float4*)&bb[0] = *(const float4*)&Bs[kk][tx * 8];
        *(float4*)&bb[4] = *(const float4*)&Bs[kk][tx * 8 + 4];
#pragma unroll
        for (int i = 0; i < 8; ++i)
#pragma unroll
            for (int j = 0; j < 8; ++j)
                acc[i][j] += a[i] * bb[j];
    }
}

// ---------------------------------------------------------------------------
// Kernel 1: fused QKV projection.
//   y[b,o,n] = sum_c W_w[o,c] * x[b,c,n] + bias_w[o],  n = p*T+t
// Written into g_{k,q,v}buf with layout [b][h][p][d*T+t], o = h*32 + d.
// Grid: (NPT/128 = 512, 6 m-tiles (3 weights x 2), B=4), 256 threads.
// ---------------------------------------------------------------------------
__global__ void __launch_bounds__(256) proj_kernel(
    const float* __restrict__ x,
    const float* __restrict__ Wk, const float* __restrict__ bk,
    const float* __restrict__ Wq, const float* __restrict__ bq,
    const float* __restrict__ Wv, const float* __restrict__ bv) {
    __shared__ float As[BK][SPAD];
    __shared__ float Bs[BK][SPAD];

    const int lt = threadIdx.x;
    const int tx = lt & 15, ty = lt >> 4;
    const int bx = blockIdx.x, mt = blockIdx.y, b = blockIdx.z;
    const int w = mt >> 1;
    const int obase = (mt & 1) * 128;

    const float* W    = (w == 0) ? Wk : (w == 1) ? Wq : Wv;
    const float* bias = (w == 0) ? bk : (w == 1) ? bq : bv;
    float* dst        = (w == 0) ? g_kbuf : (w == 1) ? g_qbuf : g_vbuf;

    const float* A  = W + (size_t)obase * NC;                    // 128 rows of W
    const float* Bm = x + (size_t)b * NC * NPT + (size_t)bx * 128;

    float acc[8][8];
#pragma unroll
    for (int i = 0; i < 8; ++i)
#pragma unroll
        for (int j = 0; j < 8; ++j) acc[i][j] = 0.0f;

    for (int k0 = 0; k0 < NC; k0 += BK) {
        load_tileT(As, A, NC, k0, lt);
        load_tileD(Bs, Bm, NPT, k0, lt);
        __syncthreads();
        mm_step(As, Bs, acc, ty, tx);
        __syncthreads();
    }

    const int n0 = bx * 128;
#pragma unroll
    for (int i = 0; i < 8; ++i) {
        const int oc = obase + ty * 8 + i;
        const int h = oc >> 5, d = oc & 31;
        const float bb = bias[oc];
        const size_t rowbase = (size_t)(b * NH + h) * NP;
#pragma unroll
        for (int j0 = 0; j0 < 8; j0 += 4) {
            const int n = n0 + tx * 8 + j0;
            const int p = n >> 6, t = n & 63;
            float4 o;
            o.x = acc[i][j0 + 0] + bb;
            o.y = acc[i][j0 + 1] + bb;
            o.z = acc[i][j0 + 2] + bb;
            o.w = acc[i][j0 + 3] + bb;
            *(float4*)&dst[(rowbase + p) * NDT + d * NT + t] = o;
        }
    }
}

// ---------------------------------------------------------------------------
// Kernel 2: energy NT-GEMM per (b,h):  E[p,q] = sum_dt K[p,dt] * Q[q,dt]
// Grid: (8, 8, 32). Output g_ebuf[z][p][q] (raw, scaled inside softmax).
// ---------------------------------------------------------------------------
__global__ void __launch_bounds__(256) energy_kernel() {
    __shared__ float As[BK][SPAD];
    __shared__ float Bs[BK][SPAD];

    const int lt = threadIdx.x;
    const int tx = lt & 15, ty = lt >> 4;
    const int z = blockIdx.z;
    const int m0 = blockIdx.y * 128;
    const int n0 = blockIdx.x * 128;

    const float* Ka = g_kbuf + (size_t)z * NP * NDT + (size_t)m0 * NDT;
    const float* Qa = g_qbuf + (size_t)z * NP * NDT + (size_t)n0 * NDT;

    float acc[8][8];
#pragma unroll
    for (int i = 0; i < 8; ++i)
#pragma unroll
        for (int j = 0; j < 8; ++j) acc[i][j] = 0.0f;

    for (int k0 = 0; k0 < NDT; k0 += BK) {
        load_tileT(As, Ka, NDT, k0, lt);
        load_tileT(Bs, Qa, NDT, k0, lt);
        __syncthreads();
        mm_step(As, Bs, acc, ty, tx);
        __syncthreads();
    }

    float* E = g_ebuf + (size_t)z * NP * NP;
#pragma unroll
    for (int i = 0; i < 8; ++i) {
        const size_t row = (size_t)(m0 + ty * 8 + i) * NP;
#pragma unroll
        for (int j0 = 0; j0 < 8; j0 += 4) {
            float4 o;
            o.x = acc[i][j0 + 0];
            o.y = acc[i][j0 + 1];
            o.z = acc[i][j0 + 2];
            o.w = acc[i][j0 + 3];
            *(float4*)&E[row + n0 + tx * 8 + j0] = o;
        }
    }
}

// ---------------------------------------------------------------------------
// Kernel 3: row softmax over q (row length 1024), in place on g_ebuf.
// One block (256 threads) per row; logits = E / sqrt(2048).
// ---------------------------------------------------------------------------
__global__ void __launch_bounds__(256) softmax_kernel() {
    const size_t row = blockIdx.x;
    float* r = g_ebuf + row * NP;
    const int lt = threadIdx.x;
    const int warp = lt >> 5, lane = lt & 31;

    float4 v = ((float4*)r)[lt];

    float m = fmaxf(fmaxf(v.x, v.y), fmaxf(v.z, v.w));
#pragma unroll
    for (int o = 16; o > 0; o >>= 1)
        m = fmaxf(m, __shfl_xor_sync(0xffffffffu, m, o));

    __shared__ float sm[8];
    if (lane == 0) sm[warp] = m;
    __syncthreads();
    float M = sm[0];
#pragma unroll
    for (int i = 1; i < 8; ++i) M = fmaxf(M, sm[i]);

    const float is = 0.022097086912079608f;  // 1/sqrt(2048)
    v.x = expf((v.x - M) * is);
    v.y = expf((v.y - M) * is);
    v.z = expf((v.z - M) * is);
    v.w = expf((v.w - M) * is);

    float s = v.x + v.y + v.z + v.w;
#pragma unroll
    for (int o = 16; o > 0; o >>= 1)
        s += __shfl_xor_sync(0xffffffffu, s, o);

    __syncthreads();  // protect sm reuse
    if (lane == 0) sm[warp] = s;
    __syncthreads();
    float S = 0.0f;
#pragma unroll
    for (int i = 0; i < 8; ++i) S += sm[i];
    const float inv = 1.0f / S;

    v.x *= inv; v.y *= inv; v.z *= inv; v.w *= inv;
    ((float4*)r)[lt] = v;
}

// ---------------------------------------------------------------------------
// Kernel 4: AV TN-GEMM per (b,h):  out[q,dt] = sum_p attn[p,q] * V[p,dt]
// Both operands are contracted over their slow axis -> both loads direct.
// Epilogue merges heads: out_final[b, h*32+d, q, t] with dt = d*64+t.
// Grid: (2048/128 = 16, 1024/128 = 8, 32).
// ---------------------------------------------------------------------------
__global__ void __launch_bounds__(256) av_kernel(float* __restrict__ out) {
    __shared__ float As[BK][SPAD];
    __shared__ float Bs[BK][SPAD];

    const int lt = threadIdx.x;
    const int tx = lt & 15, ty = lt >> 4;
    const int z = blockIdx.z;
    const int b = z >> 3, h = z & 7;
    const int m0 = blockIdx.y * 128;  // q tile
    const int n0 = blockIdx.x * 128;  // dt tile

    const float* Aa = g_ebuf + (size_t)z * NP * NP + n0 * 0 + m0;   // attn[p][q], col offset m0
    const float* Va = g_vbuf + (size_t)z * NP * NDT + n0;

    float acc[8][8];
#pragma unroll
    for (int i = 0; i < 8; ++i)
#pragma unroll
        for (int j = 0; j < 8; ++j) acc[i][j] = 0.0f;

    for (int k0 = 0; k0 < NP; k0 += BK) {
        load_tileD(As, Aa, NP, k0, lt);    // As[k][m] = attn[k0+k][m0+m]
        load_tileD(Bs, Va, NDT, k0, lt);   // Bs[k][n] = V[k0+k][n0+n]
        __syncthreads();
        mm_step(As, Bs, acc, ty, tx);
        __syncthreads();
    }

#pragma unroll
    for (int i = 0; i < 8; ++i) {
        const int q = m0 + ty * 8 + i;
#pragma unroll
        for (int j0 = 0; j0 < 8; j0 += 4) {
            const int dt = n0 + tx * 8 + j0;
            const int d = dt >> 6, t = dt & 63;
            float4 o;
            o.x = acc[i][j0 + 0];
            o.y = acc[i][j0 + 1];
            o.z = acc[i][j0 + 2];
            o.w = acc[i][j0 + 3];
            *(float4*)&out[(((size_t)(b * NC + h * ND + d)) * NP + q) * NT + t] = o;
        }
    }
}

// ---------------------------------------------------------------------------
// Launch
// ---------------------------------------------------------------------------
extern "C" void kernel_launch(void* const* d_in, const int* in_sizes, int n_in,
                              void* d_out, int out_size) {
    const float* x  = (const float*)d_in[0];
    const float* Wk = (const float*)d_in[1];
    const float* bk = (const float*)d_in[2];
    const float* Wq = (const float*)d_in[3];
    const float* bq = (const float*)d_in[4];
    const float* Wv = (const float*)d_in[5];
    const float* bv = (const float*)d_in[6];
    float* out = (float*)d_out;

    // 1) QKV projection: grid (65536/128, 3 weights * 2 m-tiles, B)
    proj_kernel<<<dim3(NPT / 128, 6, NB), 256>>>(x, Wk, bk, Wq, bq, Wv, bv);

    // 2) Energy: per (b,h) 1024x1024, k=2048
    energy_kernel<<<dim3(NP / 128, NP / 128, NB * NH), 256>>>();

    // 3) Softmax over rows
    softmax_kernel<<<NB * NH * NP, 256>>>();

    // 4) AV + head merge
    av_kernel<<<dim3(NDT / 128, NP / 128, NB * NH), 256>>>(out);
}

// round 2
// speedup vs baseline: 1.0009x; 1.0009x over previous
#include <cuda_runtime.h>
#include <cstdint>
#include <cmath>

// Problem constants
// B=4, C=256, P=1024, T=64, H=8, D=32, DT = D*T = 2048
// SCALE = sqrt(D*T) = sqrt(2048)

#define NB 4
#define NC 256
#define NP 1024
#define NT 64
#define NH 8
#define ND 32
#define NDT 2048          // D*T
#define NPT 65536         // P*T

// Scratch buffers (allocation-free rule: __device__ globals)
__device__ float g_kbuf[(size_t)NB * NH * NP * NDT];   // [b][h][p][d*T+t]
__device__ float g_qbuf[(size_t)NB * NH * NP * NDT];
__device__ float g_vbuf[(size_t)NB * NH * NP * NDT];
__device__ float g_ebuf[(size_t)NB * NH * NP * NP];    // [z][p][q] energy -> attn (in place)

// ---------------------------------------------------------------------------
// Shared GEMM micro-kernel pieces: 128x128 tile, BK=16, 256 threads, 8x8/thread
// ---------------------------------------------------------------------------
#define BK 16
#define SPAD 132   // 128 + 4 padding (132*4B = 528B rows, 16B aligned)

// Load a 128(m) x 16(k) tile from a k-contiguous (row-major, ld = Kdim) matrix,
// transposing into S[k][m]. A must be pre-offset to tile row 0 (A += m0*lda).
__device__ __forceinline__ void load_tileT(float (*S)[SPAD], const float* __restrict__ A,
                                           int lda, int k0, int lt) {
    int row = lt >> 2;              // 0..63
    int c4  = (lt & 3) * 4;         // 0,4,8,12
#pragma unroll
    for (int r = 0; r < 2; ++r) {
        int m = row + r * 64;
        float4 v = *(const float4*)(A + (size_t)m * lda + k0 + c4);
        S[c4 + 0][m] = v.x;
        S[c4 + 1][m] = v.y;
        S[c4 + 2][m] = v.z;
        S[c4 + 3][m] = v.w;
    }
}

// Load a 16(k) x 128(n) tile from an n-contiguous (row-major, ld = N) matrix
// directly into S[k][n]. B must be pre-offset to tile col 0 (B += n0).
__device__ __forceinline__ void load_tileD(float (*S)[SPAD], const float* __restrict__ Bm,
                                           int ldb, int k0, int lt) {
    int kr = lt >> 5;               // 0..7
    int c4 = (lt & 31) * 4;         // 0..124
#pragma unroll
    for (int r = 0; r < 2; ++r) {
        int k = kr + r * 8;
        float4 v = *(const float4*)(Bm + (size_t)(k0 + k) * ldb + c4);
        *(float4*)&S[k][c4] = v;
    }
}

__device__ __forceinline__ void mm_step(const float (*As)[SPAD], const float (*Bs)[SPAD],
                                        float acc[8][8], int ty, int tx) {
#pragma unroll
    for (int kk = 0; kk < BK; ++kk) {
        float a[8], bb[8];
        *(float4*)&a[0]  = *(const float4*)&As[kk][ty * 8];
        *(float4*)&a[4]  = *(const float4*)&As[kk][ty * 8 + 4];
        *(float4*)&bb[0] = *(const float4*)&Bs[kk][tx * 8];
        *(float4*)&bb[4] = *(const float4*)&Bs[kk][tx * 8 + 4];
#pragma unroll
        for (int i = 0; i < 8; ++i)
#pragma unroll
            for (int j = 0; j < 8; ++j)
                acc[i][j] += a[i] * bb[j];
    }
}

// ---------------------------------------------------------------------------
// Kernel 1: fused QKV projection.
//   y[b,o,n] = sum_c W_w[o,c] * x[b,c,n] + bias_w[o],  n = p*T+t
// Written into g_{k,q,v}buf with layout [b][h][p][d*T+t], o = h*32 + d.
// Grid: (NPT/128 = 512, 6 m-tiles (3 weights x 2), B=4), 256 threads.
// ---------------------------------------------------------------------------
__global__ void __launch_bounds__(256) proj_kernel(
    const float* __restrict__ x,
    const float* __restrict__ Wk, const float* __restrict__ bk,
    const float* __restrict__ Wq, const float* __restrict__ bq,
    const float* __restrict__ Wv, const float* __restrict__ bv) {
    __shared__ float As[BK][SPAD];
    __shared__ float Bs[BK][SPAD];

    const int lt = threadIdx.x;
    const int tx = lt & 15, ty = lt >> 4;
    const int bx = blockIdx.x, mt = blockIdx.y, b = blockIdx.z;
    const int w = mt >> 1;
    const int obase = (mt & 1) * 128;

    const float* W    = (w == 0) ? Wk : (w == 1) ? Wq : Wv;
    const float* bias = (w == 0) ? bk : (w == 1) ? bq : bv;
    float* dst        = (w == 0) ? g_kbuf : (w == 1) ? g_qbuf : g_vbuf;

    const float* A  = W + (size_t)obase * NC;                    // 128 rows of W
    const float* Bm = x + (size_t)b * NC * NPT + (size_t)bx * 128;

    float acc[8][8];
#pragma unroll
    for (int i = 0; i < 8; ++i)
#pragma unroll
        for (int j = 0; j < 8; ++j) acc[i][j] = 0.0f;

    for (int k0 = 0; k0 < NC; k0 += BK) {
        load_tileT(As, A, NC, k0, lt);
        load_tileD(Bs, Bm, NPT, k0, lt);
        __syncthreads();
        mm_step(As, Bs, acc, ty, tx);
        __syncthreads();
    }

    const int n0 = bx * 128;
#pragma unroll
    for (int i = 0; i < 8; ++i) {
        const int oc = obase + ty * 8 + i;
        const int h = oc >> 5, d = oc & 31;
        const float bb = bias[oc];
        const size_t rowbase = (size_t)(b * NH + h) * NP;
#pragma unroll
        for (int j0 = 0; j0 < 8; j0 += 4) {
            const int n = n0 + tx * 8 + j0;
            const int p = n >> 6, t = n & 63;
            float4 o;
            o.x = acc[i][j0 + 0] + bb;
            o.y = acc[i][j0 + 1] + bb;
            o.z = acc[i][j0 + 2] + bb;
            o.w = acc[i][j0 + 3] + bb;
            *(float4*)&dst[(rowbase + p) * NDT + d * NT + t] = o;
        }
    }
}

// ---------------------------------------------------------------------------
// Kernel 2: energy NT-GEMM per (b,h):  E[p,q] = sum_dt K[p,dt] * Q[q,dt]
// Grid: (8, 8, 32). Output g_ebuf[z][p][q] (raw, scaled inside softmax).
// ---------------------------------------------------------------------------
__global__ void __launch_bounds__(256) energy_kernel() {
    __shared__ float As[BK][SPAD];
    __shared__ float Bs[BK][SPAD];

    const int lt = threadIdx.x;
    const int tx = lt & 15, ty = lt >> 4;
    const int z = blockIdx.z;
    const int m0 = blockIdx.y * 128;
    const int n0 = blockIdx.x * 128;

    const float* Ka = g_kbuf + (size_t)z * NP * NDT + (size_t)m0 * NDT;
    const float* Qa = g_qbuf + (size_t)z * NP * NDT + (size_t)n0 * NDT;

    float acc[8][8];
#pragma unroll
    for (int i = 0; i < 8; ++i)
#pragma unroll
        for (int j = 0; j < 8; ++j) acc[i][j] = 0.0f;

    for (int k0 = 0; k0 < NDT; k0 += BK) {
        load_tileT(As, Ka, NDT, k0, lt);
        load_tileT(Bs, Qa, NDT, k0, lt);
        __syncthreads();
        mm_step(As, Bs, acc, ty, tx);
        __syncthreads();
    }

    float* E = g_ebuf + (size_t)z * NP * NP;
#pragma unroll
    for (int i = 0; i < 8; ++i) {
        const size_t row = (size_t)(m0 + ty * 8 + i) * NP;
#pragma unroll
        for (int j0 = 0; j0 < 8; j0 += 4) {
            float4 o;
            o.x = acc[i][j0 + 0];
            o.y = acc[i][j0 + 1];
            o.z = acc[i][j0 + 2];
            o.w = acc[i][j0 + 3];
            *(float4*)&E[row + n0 + tx * 8 + j0] = o;
        }
    }
}

// ---------------------------------------------------------------------------
// Kernel 3: row softmax over q (row length 1024), in place on g_ebuf.
// One block (256 threads) per row; logits = E / sqrt(2048).
// ---------------------------------------------------------------------------
__global__ void __launch_bounds__(256) softmax_kernel() {
    const size_t row = blockIdx.x;
    float* r = g_ebuf + row * NP;
    const int lt = threadIdx.x;
    const int warp = lt >> 5, lane = lt & 31;

    float4 v = ((float4*)r)[lt];

    float m = fmaxf(fmaxf(v.x, v.y), fmaxf(v.z, v.w));
#pragma unroll
    for (int o = 16; o > 0; o >>= 1)
        m = fmaxf(m, __shfl_xor_sync(0xffffffffu, m, o));

    __shared__ float sm[8];
    if (lane == 0) sm[warp] = m;
    __syncthreads();
    float M = sm[0];
#pragma unroll
    for (int i = 1; i < 8; ++i) M = fmaxf(M, sm[i]);

    const float is = 0.022097086912079608f;  // 1/sqrt(2048)
    v.x = expf((v.x - M) * is);
    v.y = expf((v.y - M) * is);
    v.z = expf((v.z - M) * is);
    v.w = expf((v.w - M) * is);

    float s = v.x + v.y + v.z + v.w;
#pragma unroll
    for (int o = 16; o > 0; o >>= 1)
        s += __shfl_xor_sync(0xffffffffu, s, o);

    __syncthreads();  // protect sm reuse
    if (lane == 0) sm[warp] = s;
    __syncthreads();
    float S = 0.0f;
#pragma unroll
    for (int i = 0; i < 8; ++i) S += sm[i];
    const float inv = 1.0f / S;

    v.x *= inv; v.y *= inv; v.z *= inv; v.w *= inv;
    ((float4*)r)[lt] = v;
}

// ---------------------------------------------------------------------------
// Kernel 4: AV TN-GEMM per (b,h):  out[q,dt] = sum_p attn[p,q] * V[p,dt]
// Both operands are contracted over their slow axis -> both loads direct.
// Epilogue merges heads: out_final[b, h*32+d, q, t] with dt = d*64+t.
// Grid: (2048/128 = 16, 1024/128 = 8, 32).
// ---------------------------------------------------------------------------
__global__ void __launch_bounds__(256) av_kernel(float* __restrict__ out) {
    __shared__ float As[BK][SPAD];
    __shared__ float Bs[BK][SPAD];

    const int lt = threadIdx.x;
    const int tx = lt & 15, ty = lt >> 4;
    const int z = blockIdx.z;
    const int b = z >> 3, h = z & 7;
    const int m0 = blockIdx.y * 128;  // q tile
    const int n0 = blockIdx.x * 128;  // dt tile

    const float* Aa = g_ebuf + (size_t)z * NP * NP + n0 * 0 + m0;   // attn[p][q], col offset m0
    const float* Va = g_vbuf + (size_t)z * NP * NDT + n0;

    float acc[8][8];
#pragma unroll
    for (int i = 0; i < 8; ++i)
#pragma unroll
        for (int j = 0; j < 8; ++j) acc[i][j] = 0.0f;

    for (int k0 = 0; k0 < NP; k0 += BK) {
        load_tileD(As, Aa, NP, k0, lt);    // As[k][m] = attn[k0+k][m0+m]
        load_tileD(Bs, Va, NDT, k0, lt);   // Bs[k][n] = V[k0+k][n0+n]
        __syncthreads();
        mm_step(As, Bs, acc, ty, tx);
        __syncthreads();
    }

#pragma unroll
    for (int i = 0; i < 8; ++i) {
        const int q = m0 + ty * 8 + i;
#pragma unroll
        for (int j0 = 0; j0 < 8; j0 += 4) {
            const int dt = n0 + tx * 8 + j0;
            const int d = dt >> 6, t = dt & 63;
            float4 o;
            o.x = acc[i][j0 + 0];
            o.y = acc[i][j0 + 1];
            o.z = acc[i][j0 + 2];
            o.w = acc[i][j0 + 3];
            *(float4*)&out[(((size_t)(b * NC + h * ND + d)) * NP + q) * NT + t] = o;
        }
    }
}

// ---------------------------------------------------------------------------
// Launch
// ---------------------------------------------------------------------------
extern "C" void kernel_launch(void* const* d_in, const int* in_sizes, int n_in,
                              void* d_out, int out_size) {
    const float* x  = (const float*)d_in[0];
    const float* Wk = (const float*)d_in[1];
    const float* bk = (const float*)d_in[2];
    const float* Wq = (const float*)d_in[3];
    const float* bq = (const float*)d_in[4];
    const float* Wv = (const float*)d_in[5];
    const float* bv = (const float*)d_in[6];
    float* out = (float*)d_out;

    // 1) QKV projection: grid (65536/128, 3 weights * 2 m-tiles, B)
    proj_kernel<<<dim3(NPT / 128, 6, NB), 256>>>(x, Wk, bk, Wq, bq, Wv, bv);

    // 2) Energy: per (b,h) 1024x1024, k=2048
    energy_kernel<<<dim3(NP / 128, NP / 128, NB * NH), 256>>>();

    // 3) Softmax over rows
    softmax_kernel<<<NB * NH * NP, 256>>>();

    // 4) AV + head merge
    av_kernel<<<dim3(NDT / 128, NP / 128, NB * NH), 256>>>(out);
}

// round 6
// speedup vs baseline: 2.0234x; 2.0217x over previous
#include <cuda_runtime.h>
#include <cstdint>

// B=4, C=256, P=1024, T=64, H=8, D=32, DT=2048
#define NB 4
#define NC 256
#define NP 1024
#define NT 64
#define NH 8
#define ND 32
#define NDT 2048
#define NPT 65536

// Scratch (__device__ globals per allocation-free rule)
__device__ float g_kbuf[(size_t)NB * NH * NP * NDT];   // [z][p][d*64+t]
__device__ float g_qbuf[(size_t)NB * NH * NP * NDT];   // [z][q][d*64+t]
__device__ float g_vbuf[(size_t)NB * NH * NP * NDT];   // [z][p][d*64+t]
__device__ float g_vtbuf[(size_t)NB * NH * NDT * NP];  // [z][dt][p] (scaled by invS[p])
__device__ float g_ebuf[(size_t)NB * NH * NP * NP];    // [z][q][p]  E' -> exp in place
__device__ float g_sbuf[(size_t)NB * NH * NP];         // invS per (z, p)

// Fragment-packed staging:
//  A: 16 regions (mb 0..7, kb 0..1), stride 136 floats (128 used + 8 bank pad)
//  B: 32 regions (nb 0..15, kb 0..1), stride 72 floats (64 used + 8 bank pad)
#define A_STRIDE 136
#define B_STRIDE 72
#define B_BASE   (16 * A_STRIDE)                 // 2176 floats
#define STAGE_F  (B_BASE + 32 * B_STRIDE)        // 4480 floats per stage
// Epilogue staging (two-pass): per warp 32n x (32m + 1 pad)
#define CS_F     (8 * 32 * 33)                   // 8448 floats
#define SMEM_SZ  (2 * STAGE_F * 4)               // 35840 B (> CS_F*4 = 33792)

__device__ __forceinline__ int swsl(int l) { return l ^ (l >> 3); }

__device__ __forceinline__ float tf32r(float x) {
    uint32_t o;
    asm("cvt.rna.tf32.f32 %0, %1;" : "=r"(o) : "f"(x));
    return __uint_as_float(o);
}

#define MMA8(c, a, b) asm volatile( \
    "mma.sync.aligned.m16n8k8.row.col.f32.tf32.tf32.f32 " \
    "{%0,%1,%2,%3}, {%4,%5,%6,%7}, {%8,%9}, {%0,%1,%2,%3};" \
    : "+f"((c)[0]), "+f"((c)[1]), "+f"((c)[2]), "+f"((c)[3]) \
    : "r"((a)[0]), "r"((a)[1]), "r"((a)[2]), "r"((a)[3]), \
      "r"((b)[0]), "r"((b)[1]))

// ---------------------------------------------------------------------------
// Shared mainloop: acc[4][4][4] += A[128m x K] . B[128n x K]^T (NT), tf32.
// A k-contiguous (lda floats). B: if XT, logical B[n][k] = Bx[k*ldb + n]
// (transpose during STS); else k-contiguous like A.
// CTA 128x128, BK=16, 8 warps, warp tile 64m x 32n.
// ---------------------------------------------------------------------------
template <int XT>
__device__ __forceinline__ void run_gemm(float* sm, const float* __restrict__ Ag,
                                         size_t lda, const float* __restrict__ Bg,
                                         size_t ldb, int nk, float acc[4][4][4]) {
    const int tid = threadIdx.x, lane = tid & 31, ww = tid >> 5;
    const int wmi = (ww >> 2) * 4;   // A region base (m): 0 or 4
    const int wni = (ww & 3) * 4;    // B region base (n): 0,4,8,12

#pragma unroll
    for (int i = 0; i < 4; ++i)
#pragma unroll
        for (int j = 0; j < 4; ++j)
#pragma unroll
            for (int r = 0; r < 4; ++r) acc[i][j][r] = 0.0f;

    // per-thread A ldg mapping: row pair (ar0, ar0+64), k-quad aqd (4 floats)
    const int ar0 = tid >> 2, aqd = tid & 3;
    // B XT mapping: column n, k-octet half
    const int xn = tid & 127, xkh = tid >> 7;

    float4 va[2], vb[2];
    float rx[8];

#define LDG_AB(c)                                                              \
    {                                                                          \
        const float* ap = Ag + (size_t)(c) * 16;                               \
        va[0] = *(const float4*)(ap + (size_t)ar0 * lda + aqd * 4);            \
        va[1] = *(const float4*)(ap + (size_t)(ar0 + 64) * lda + aqd * 4);     \
        if (XT) {                                                              \
            const float* bp = Bg + (size_t)((c) * 16 + xkh * 8) * ldb + xn;    \
            _Pragma("unroll") for (int j = 0; j < 8; ++j)                      \
                rx[j] = bp[(size_t)j * ldb];                                   \
        } else {                                                               \
            const float* bp = Bg + (size_t)(c) * 16;                           \
            vb[0] = *(const float4*)(bp + (size_t)ar0 * ldb + aqd * 4);        \
            vb[1] = *(const float4*)(bp + (size_t)(ar0 + 64) * ldb + aqd * 4); \
        }                                                                      \
    }

#define STS_AB(st)                                                             \
    {                                                                          \
        float* stg = sm + (st) * STAGE_F;                                      \
        _Pragma("unroll") for (int i = 0; i < 2; ++i)                          \
        {                                                                      \
            int r = ar0 + i * 64;                                              \
            int mb = r >> 4, rr = r & 15, g = rr & 7, mh = rr >> 3;            \
            int kb = aqd >> 1, ch = aqd & 1;                                   \
            float* ba = stg + (mb * 2 + kb) * A_STRIDE + mh + 2 * ch;          \
            ba[swsl(g * 4 + 0) * 4] = tf32r(va[i].x);                          \
            ba[swsl(g * 4 + 1) * 4] = tf32r(va[i].y);                          \
            ba[swsl(g * 4 + 2) * 4] = tf32r(va[i].z);                          \
            ba[swsl(g * 4 + 3) * 4] = tf32r(va[i].w);                          \
        }                                                                      \
        if (XT) {                                                              \
            int nb = xn >> 3, g = xn & 7;                                      \
            float* bb = stg + B_BASE + (nb * 2 + xkh) * B_STRIDE;              \
            _Pragma("unroll") for (int j = 0; j < 8; ++j)                      \
                bb[swsl(g * 4 + (j & 3)) * 2 + (j >> 2)] = tf32r(rx[j]);       \
        } else {                                                               \
            _Pragma("unroll") for (int i = 0; i < 2; ++i)                      \
            {                                                                  \
                int r = ar0 + i * 64;                                          \
                int nb = r >> 3, g = r & 7;                                    \
                int kb = aqd >> 1, kh = aqd & 1;                               \
                float* bb = stg + B_BASE + (nb * 2 + kb) * B_STRIDE + kh;      \
                bb[swsl(g * 4 + 0) * 2] = tf32r(vb[i].x);                      \
                bb[swsl(g * 4 + 1) * 2] = tf32r(vb[i].y);                      \
                bb[swsl(g * 4 + 2) * 2] = tf32r(vb[i].z);                      \
                bb[swsl(g * 4 + 3) * 2] = tf32r(vb[i].w);                      \
            }                                                                  \
        }                                                                      \
    }

    LDG_AB(0);
    STS_AB(0);
    __syncthreads();

    const int sla = swsl(lane) * 4;
    const int slb = swsl(lane) * 2;

    for (int c = 0; c < nk; ++c) {
        if (c + 1 < nk) LDG_AB(c + 1);

        const float* sa = sm + (c & 1) * STAGE_F;
        const float* sb = sa + B_BASE;
        uint32_t af[4][4], bf[4][2];
#pragma unroll
        for (int kb = 0; kb < 2; ++kb) {
#pragma unroll
            for (int i = 0; i < 4; ++i) {
                uint4 u = *(const uint4*)(sa + ((wmi + i) * 2 + kb) * A_STRIDE + sla);
                af[i][0] = u.x; af[i][1] = u.y; af[i][2] = u.z; af[i][3] = u.w;
            }
#pragma unroll
            for (int i = 0; i < 4; ++i) {
                uint2 u = *(const uint2*)(sb + ((wni + i) * 2 + kb) * B_STRIDE + slb);
                bf[i][0] = u.x; bf[i][1] = u.y;
            }
#pragma unroll
            for (int i = 0; i < 4; ++i)
#pragma unroll
                for (int j = 0; j < 4; ++j) MMA8(acc[i][j], af[i], bf[j]);
        }
        __syncthreads();
        if (c + 1 < nk) {
            STS_AB((c + 1) & 1);
            __syncthreads();
        }
    }
#undef LDG_AB
#undef STS_AB
}

// Stage one 32-row m-half of the warp accumulators into per-warp
// Cs[n(32)][m(32)+pad] (stride 33). half=0: m 0..31 (acc i=0,1);
// half=1: m 32..63 (acc i=2,3). Warp-private region; __syncwarp orders.
__device__ __forceinline__ float* stage_cs_half(float* sm, float acc[4][4][4],
                                                int half) {
    const int tid = threadIdx.x, lane = tid & 31, ww = tid >> 5;
    float* Cs = sm + ww * (32 * 33);
    const int g = lane >> 2, q = lane & 3;
    __syncwarp();
#pragma unroll
    for (int i = 0; i < 2; ++i) {
        const int i2 = half * 2 + i;
#pragma unroll
        for (int j = 0; j < 4; ++j) {
            float* cp = Cs + (j * 8 + q * 2) * 33 + i * 16 + g;
            cp[0] = acc[i2][j][0];
            cp[33] = acc[i2][j][1];
            cp[8] = acc[i2][j][2];
            cp[33 + 8] = acc[i2][j][3];
        }
    }
    __syncwarp();
    return Cs;
}

// ---------------------------------------------------------------------------
// Kernel 1: QKV projection. grid(512, 6, 4): n-tile, (w*2+mt), b.
// Y[oc][n] = sum_c W[oc][c] * x[b][c][n] + bias[oc]; n = p*64+t, oc = h*32+d.
// ---------------------------------------------------------------------------
__global__ void __launch_bounds__(256) proj_tc(
    const float* __restrict__ x,
    const float* __restrict__ Wk, const float* __restrict__ bk,
    const float* __restrict__ Wq, const float* __restrict__ bq,
    const float* __restrict__ Wv, const float* __restrict__ bv) {
    extern __shared__ float sm[];
    const int tid = threadIdx.x, lane = tid & 31, ww = tid >> 5;
    const int w = blockIdx.y >> 1, mt = blockIdx.y & 1, b = blockIdx.z;
    const int n0 = blockIdx.x * 128;
    const int obase = mt * 128;

    const float* W    = (w == 0) ? Wk : (w == 1) ? Wq : Wv;
    const float* bias = (w == 0) ? bk : (w == 1) ? bq : bv;
    float* dst        = (w == 0) ? g_kbuf : (w == 1) ? g_qbuf : g_vbuf;

    float acc[4][4][4];
    run_gemm<1>(sm, W + (size_t)obase * NC, NC,
                x + (size_t)b * NC * NPT + n0, NPT, NC / 16, acc);

    const int wmb = (ww >> 2) * 64, wnb = (ww & 3) * 32;
    const int nw = n0 + wnb;
    const int p = nw >> 6, tbase = nw & 63;  // 32-chunk stays within one t-block
    for (int half = 0; half < 2; ++half) {
        float* Cs = stage_cs_half(sm, acc, half);
#pragma unroll 4
        for (int mr = 0; mr < 32; ++mr) {
            const int oc = obase + wmb + half * 32 + mr;
            const int h = oc >> 5, d = oc & 31;
            dst[((size_t)(b * NH + h) * NP + p) * NDT + d * 64 + tbase + lane] =
                Cs[lane * 33 + mr] + bias[oc];
        }
    }
}

// ---------------------------------------------------------------------------
// Kernel 2: energy E'[z][q][p] = sum_dt Q[q,dt] * K[p,dt]. grid(8, 8, 32).
// ---------------------------------------------------------------------------
__global__ void __launch_bounds__(256) energy_tc() {
    extern __shared__ float sm[];
    const int tid = threadIdx.x, lane = tid & 31, ww = tid >> 5;
    const int z = blockIdx.z;
    const int m0 = blockIdx.y * 128;   // q
    const int n0 = blockIdx.x * 128;   // p

    float acc[4][4][4];
    run_gemm<0>(sm, g_qbuf + (size_t)z * NP * NDT + (size_t)m0 * NDT, NDT,
                g_kbuf + (size_t)z * NP * NDT + (size_t)n0 * NDT, NDT,
                NDT / 16, acc);

    const int wmb = (ww >> 2) * 64, wnb = (ww & 3) * 32;
    float* e = g_ebuf + (size_t)z * NP * NP + n0 + wnb + lane;
    for (int half = 0; half < 2; ++half) {
        float* Cs = stage_cs_half(sm, acc, half);
#pragma unroll 4
        for (int mr = 0; mr < 32; ++mr) {
            const int q = m0 + wmb + half * 32 + mr;
            e[(size_t)q * NP] = Cs[lane * 33 + mr];
        }
    }
}

// ---------------------------------------------------------------------------
// Kernel 3: softmax over q (unnormalized): e <- exp(e/sqrt(2048)),
// invS[z][p] = 1/sum_q. Logits are O(1) -> no max subtraction needed.
// ---------------------------------------------------------------------------
__global__ void __launch_bounds__(256) softmax_tc() {
    const int z = blockIdx.y;
    const int p = blockIdx.x * 256 + threadIdx.x;
    float* e = g_ebuf + (size_t)z * NP * NP + p;
    const float is = 0.022097086912079608f;  // 1/sqrt(2048)
    float s = 0.0f;
    for (int q = 0; q < NP; q += 4) {
        float v0 = e[(size_t)(q + 0) * NP];
        float v1 = e[(size_t)(q + 1) * NP];
        float v2 = e[(size_t)(q + 2) * NP];
        float v3 = e[(size_t)(q + 3) * NP];
        v0 = __expf(v0 * is); v1 = __expf(v1 * is);
        v2 = __expf(v2 * is); v3 = __expf(v3 * is);
        e[(size_t)(q + 0) * NP] = v0;
        e[(size_t)(q + 1) * NP] = v1;
        e[(size_t)(q + 2) * NP] = v2;
        e[(size_t)(q + 3) * NP] = v3;
        s += (v0 + v1) + (v2 + v3);
    }
    g_sbuf[(size_t)z * NP + p] = 1.0f / s;
}

// ---------------------------------------------------------------------------
// Kernel 4: vt[z][dt][p] = v[z][p][dt] * invS[p].  grid(32, 16, 32).
// ---------------------------------------------------------------------------
__global__ void __launch_bounds__(256) vtrans_tc() {
    __shared__ float ts[64][68];
    const int tid = threadIdx.x;
    const int z = blockIdx.z;
    const int dt0 = blockIdx.x * 64;
    const int p0 = blockIdx.y * 64;

    const float* in = g_vbuf + (size_t)z * NP * NDT;
    const float* invS = g_sbuf + (size_t)z * NP;
#pragma unroll
    for (int i = 0; i < 4; ++i) {
        int idx = i * 256 + tid;
        int r = idx >> 4, c4 = (idx & 15) * 4;
        float sc = invS[p0 + r];
        float4 v = *(const float4*)(in + (size_t)(p0 + r) * NDT + dt0 + c4);
        ts[r][c4 + 0] = v.x * sc;
        ts[r][c4 + 1] = v.y * sc;
        ts[r][c4 + 2] = v.z * sc;
        ts[r][c4 + 3] = v.w * sc;
    }
    __syncthreads();
    float* out = g_vtbuf + (size_t)z * NDT * NP;
#pragma unroll
    for (int i = 0; i < 4; ++i) {
        int idx = i * 256 + tid;
        int r = idx >> 4, c4 = (idx & 15) * 4;
        float4 w;
        w.x = ts[c4 + 0][r];
        w.y = ts[c4 + 1][r];
        w.z = ts[c4 + 2][r];
        w.w = ts[c4 + 3][r];
        *(float4*)(out + (size_t)(dt0 + r) * NP + p0 + c4) = w;
    }
}

// ---------------------------------------------------------------------------
// Kernel 5: AV. O'[dt][q] = sum_p Vt[dt][p] * attn'[q][p]. grid(8, 16, 32).
// Writes out[b][h*32+d][q][t], coalesced (lanes along t).
// ---------------------------------------------------------------------------
__global__ void __launch_bounds__(256) av_tc(float* __restrict__ out) {
    extern __shared__ float sm[];
    const int tid = threadIdx.x, lane = tid & 31, ww = tid >> 5;
    const int z = blockIdx.z, b = z >> 3, h = z & 7;
    const int m0 = blockIdx.y * 128;  // dt
    const int n0 = blockIdx.x * 128;  // q

    float acc[4][4][4];
    run_gemm<0>(sm, g_vtbuf + (size_t)z * NDT * NP + (size_t)m0 * NP, NP,
                g_ebuf + (size_t)z * NP * NP + (size_t)n0 * NP, NP,
                NP / 16, acc);

    const int wmb = (ww >> 2) * 64, wnb = (ww & 3) * 32;
    const int dtb = m0 + wmb;            // multiple of 64 -> single d, t=0..63
    const int d = dtb >> 6;
    float* ob = out + ((size_t)(b * NC) + h * ND + d) * NP * NT;
    for (int half = 0; half < 2; ++half) {
        float* Cs = stage_cs_half(sm, acc, half);  // m half*32+lane -> t
#pragma unroll 4
        for (int nn = 0; nn < 32; ++nn) {
            const size_t qoff = (size_t)(n0 + wnb + nn) * NT;
            ob[qoff + half * 32 + lane] = Cs[nn * 33 + lane];
        }
    }
}

// ---------------------------------------------------------------------------
extern "C" void kernel_launch(void* const* d_in, const int* in_sizes, int n_in,
                              void* d_out, int out_size) {
    const float* x  = (const float*)d_in[0];
    const float* Wk = (const float*)d_in[1];
    const float* bk = (const float*)d_in[2];
    const float* Wq = (const float*)d_in[3];
    const float* bq = (const float*)d_in[4];
    const float* Wv = (const float*)d_in[5];
    const float* bv = (const float*)d_in[6];
    float* out = (float*)d_out;

    proj_tc<<<dim3(NPT / 128, 6, NB), 256, SMEM_SZ>>>(x, Wk, bk, Wq, bq, Wv, bv);
    energy_tc<<<dim3(NP / 128, NP / 128, NB * NH), 256, SMEM_SZ>>>();
    softmax_tc<<<dim3(NP / 256, NB * NH), 256>>>();
    vtrans_tc<<<dim3(NDT / 64, NP / 64, NB * NH), 256>>>();
    av_tc<<<dim3(NP / 128, NDT / 128, NB * NH), 256, SMEM_SZ>>>(out);
}

// round 7
// speedup vs baseline: 2.3606x; 1.1666x over previous
#include <cuda_runtime.h>
#include <cstdint>

// B=4, C=256, P=1024, T=64, H=8, D=32, DT=2048
#define NB 4
#define NC 256
#define NP 1024
#define NT 64
#define NH 8
#define ND 32
#define NDT 2048
#define NPT 65536

// Scratch (__device__ globals per allocation-free rule)
__device__ float g_kbuf[(size_t)NB * NH * NP * NDT];   // [z][p][d*64+t]
__device__ float g_qbuf[(size_t)NB * NH * NP * NDT];   // [z][q][d*64+t]
__device__ float g_vbuf[(size_t)NB * NH * NP * NDT];   // [z][p][d*64+t]
__device__ float g_ebuf[(size_t)NB * NH * NP * NP];    // [z][q][p]  E' -> exp in place
__device__ float g_sbuf[(size_t)NB * NH * NP];         // invS per (z, p)

// Fragment-packed staging (tile 256m x 128n, BK=16):
//  A: 32 regions (mb 0..15, kb 0..1), stride 136 floats (128 used + 8 pad)
//  B: 32 regions (nb 0..15, kb 0..1), stride 72 floats (64 used + 8 pad)
#define A_STRIDE 136
#define B_STRIDE 72
#define B_BASE   (32 * A_STRIDE)                 // 4352 floats
#define STAGE_F  (B_BASE + 32 * B_STRIDE)        // 6656 floats per stage
// Epilogue staging (two-pass): per warp 32n x (32m + 1 pad), 16 warps
#define CS_F     (16 * 32 * 33)                  // 16896 floats
#define SMEM_SZ  (CS_F * 4)                      // 67584 B (> 2*STAGE_F*4 = 53248)

__device__ __forceinline__ int swsl(int l) { return l ^ (l >> 3); }

__device__ __forceinline__ float tf32r(float x) {
    uint32_t o;
    asm("cvt.rna.tf32.f32 %0, %1;" : "=r"(o) : "f"(x));
    return __uint_as_float(o);
}

#define MMA8(c, a, b) asm volatile( \
    "mma.sync.aligned.m16n8k8.row.col.f32.tf32.tf32.f32 " \
    "{%0,%1,%2,%3}, {%4,%5,%6,%7}, {%8,%9}, {%0,%1,%2,%3};" \
    : "+f"((c)[0]), "+f"((c)[1]), "+f"((c)[2]), "+f"((c)[3]) \
    : "r"((a)[0]), "r"((a)[1]), "r"((a)[2]), "r"((a)[3]), \
      "r"((b)[0]), "r"((b)[1]))

// ---------------------------------------------------------------------------
// Shared mainloop: acc[4][4][4] += A[256m x K] . B[128n x K]^T (NT), tf32.
// A k-contiguous (lda floats); if SCA, A row values are scaled by Asc[k].
// B: if XT, logical B[n][k] = Bx[k*ldb + n] (transpose during STS);
// else k-contiguous like A.
// CTA 256x128, BK=16, 16 warps (4m x 4n), warp tile 64m x 32n.
// One __syncthreads per chunk (STS targets the non-active buffer).
// ---------------------------------------------------------------------------
template <int XT, int SCA>
__device__ __forceinline__ void run_gemm(float* sm, const float* __restrict__ Ag,
                                         size_t lda, const float* __restrict__ Asc,
                                         const float* __restrict__ Bg,
                                         size_t ldb, int nk, float acc[4][4][4]) {
    const int tid = threadIdx.x, lane = tid & 31, ww = tid >> 5;
    const int wmi = (ww >> 2) * 4;   // A region base (mb): 0,4,8,12
    const int wni = (ww & 3) * 4;    // B region base (nb): 0,4,8,12

#pragma unroll
    for (int i = 0; i < 4; ++i)
#pragma unroll
        for (int j = 0; j < 4; ++j)
#pragma unroll
            for (int r = 0; r < 4; ++r) acc[i][j][r] = 0.0f;

    // A ldg: row pair (ar0, ar0+128), k-quad aqd (4 floats each)
    const int ar0 = tid >> 2, aqd = tid & 3;
    // B XT: column n = xn, k-quad xkh (0..3)
    const int xn = tid & 127, xkh = tid >> 7;

    float4 va[2], vb;
    float rx[4];

#define LDG_AB(c)                                                              \
    {                                                                          \
        const float* ap = Ag + (size_t)(c) * 16;                               \
        va[0] = *(const float4*)(ap + (size_t)ar0 * lda + aqd * 4);            \
        va[1] = *(const float4*)(ap + (size_t)(ar0 + 128) * lda + aqd * 4);    \
        if (SCA) {                                                             \
            float4 s4 = *(const float4*)(Asc + (c) * 16 + aqd * 4);            \
            va[0].x *= s4.x; va[0].y *= s4.y; va[0].z *= s4.z; va[0].w *= s4.w;\
            va[1].x *= s4.x; va[1].y *= s4.y; va[1].z *= s4.z; va[1].w *= s4.w;\
        }                                                                      \
        if (XT) {                                                              \
            const float* bp = Bg + (size_t)((c) * 16 + xkh * 4) * ldb + xn;    \
            _Pragma("unroll") for (int j = 0; j < 4; ++j)                      \
                rx[j] = bp[(size_t)j * ldb];                                   \
        } else {                                                               \
            const float* bp = Bg + (size_t)(c) * 16;                          \
            vb = *(const float4*)(bp + (size_t)(tid >> 2) * ldb + aqd * 4);    \
        }                                                                      \
    }

#define STS_AB(st)                                                             \
    {                                                                          \
        float* stg = sm + (st) * STAGE_F;                                      \
        _Pragma("unroll") for (int i = 0; i < 2; ++i)                          \
        {                                                                      \
            int r = ar0 + i * 128;                                             \
            int mb = r >> 4, rr = r & 15, g = rr & 7, mh = rr >> 3;            \
            int kb = aqd >> 1, ch = aqd & 1;                                   \
            float* ba = stg + (mb * 2 + kb) * A_STRIDE + mh + 2 * ch;          \
            ba[swsl(g * 4 + 0) * 4] = tf32r(va[i].x);                          \
            ba[swsl(g * 4 + 1) * 4] = tf32r(va[i].y);                          \
            ba[swsl(g * 4 + 2) * 4] = tf32r(va[i].z);                          \
            ba[swsl(g * 4 + 3) * 4] = tf32r(va[i].w);                          \
        }                                                                      \
        if (XT) {                                                              \
            int nb = xn >> 3, g = xn & 7;                                      \
            int kb = xkh >> 1, kh = xkh & 1;                                   \
            float* bb = stg + B_BASE + (nb * 2 + kb) * B_STRIDE + kh;          \
            _Pragma("unroll") for (int j = 0; j < 4; ++j)                      \
                bb[swsl(g * 4 + j) * 2] = tf32r(rx[j]);                        \
        } else {                                                               \
            int r = tid >> 2;                                                  \
            int nb = r >> 3, g = r & 7;                                        \
            int kb = aqd >> 1, kh = aqd & 1;                                   \
            float* bb = stg + B_BASE + (nb * 2 + kb) * B_STRIDE + kh;          \
            bb[swsl(g * 4 + 0) * 2] = tf32r(vb.x);                             \
            bb[swsl(g * 4 + 1) * 2] = tf32r(vb.y);                             \
            bb[swsl(g * 4 + 2) * 2] = tf32r(vb.z);                             \
            bb[swsl(g * 4 + 3) * 2] = tf32r(vb.w);                             \
        }                                                                      \
    }

    LDG_AB(0);
    STS_AB(0);
    __syncthreads();

    const int sla = swsl(lane) * 4;
    const int slb = swsl(lane) * 2;

    for (int c = 0; c < nk; ++c) {
        if (c + 1 < nk) LDG_AB(c + 1);

        const float* sa = sm + (c & 1) * STAGE_F;
        const float* sb = sa + B_BASE;
        uint32_t af[4][4], bf[4][2];
#pragma unroll
        for (int kb = 0; kb < 2; ++kb) {
#pragma unroll
            for (int i = 0; i < 4; ++i) {
                uint4 u = *(const uint4*)(sa + ((wmi + i) * 2 + kb) * A_STRIDE + sla);
                af[i][0] = u.x; af[i][1] = u.y; af[i][2] = u.z; af[i][3] = u.w;
            }
#pragma unroll
            for (int i = 0; i < 4; ++i) {
                uint2 u = *(const uint2*)(sb + ((wni + i) * 2 + kb) * B_STRIDE + slb);
                bf[i][0] = u.x; bf[i][1] = u.y;
            }
#pragma unroll
            for (int i = 0; i < 4; ++i)
#pragma unroll
                for (int j = 0; j < 4; ++j) MMA8(acc[i][j], af[i], bf[j]);
        }
        if (c + 1 < nk) STS_AB((c + 1) & 1);   // writes the other buffer
        __syncthreads();                        // single barrier per chunk
    }
#undef LDG_AB
#undef STS_AB
}

// Stage one 32-row m-half of the warp accumulators into per-warp
// Cs[n(32)][m(32)+pad] (stride 33). half=0: m 0..31; half=1: m 32..63.
__device__ __forceinline__ float* stage_cs_half(float* sm, float acc[4][4][4],
                                                int half) {
    const int tid = threadIdx.x, lane = tid & 31, ww = tid >> 5;
    float* Cs = sm + ww * (32 * 33);
    const int g = lane >> 2, q = lane & 3;
    __syncwarp();
#pragma unroll
    for (int i = 0; i < 2; ++i) {
        const int i2 = half * 2 + i;
#pragma unroll
        for (int j = 0; j < 4; ++j) {
            float* cp = Cs + (j * 8 + q * 2) * 33 + i * 16 + g;
            cp[0] = acc[i2][j][0];
            cp[33] = acc[i2][j][1];
            cp[8] = acc[i2][j][2];
            cp[33 + 8] = acc[i2][j][3];
        }
    }
    __syncwarp();
    return Cs;
}

// ---------------------------------------------------------------------------
// Kernel 1: QKV projection. grid(512, 3, 4): n-tile, w, b. 512 threads.
// Y[oc][n] = sum_c W[oc][c] * x[b][c][n] + bias[oc]; n = p*64+t, oc = h*32+d.
// ---------------------------------------------------------------------------
__global__ void __launch_bounds__(512) proj_tc(
    const float* __restrict__ x,
    const float* __restrict__ Wk, const float* __restrict__ bk,
    const float* __restrict__ Wq, const float* __restrict__ bq,
    const float* __restrict__ Wv, const float* __restrict__ bv) {
    extern __shared__ float sm[];
    const int tid = threadIdx.x, lane = tid & 31, ww = tid >> 5;
    const int w = blockIdx.y, b = blockIdx.z;
    const int n0 = blockIdx.x * 128;

    const float* W    = (w == 0) ? Wk : (w == 1) ? Wq : Wv;
    const float* bias = (w == 0) ? bk : (w == 1) ? bq : bv;
    float* dst        = (w == 0) ? g_kbuf : (w == 1) ? g_qbuf : g_vbuf;

    float acc[4][4][4];
    run_gemm<1, 0>(sm, W, NC, nullptr,
                   x + (size_t)b * NC * NPT + n0, NPT, NC / 16, acc);

    const int wmb = (ww >> 2) * 64, wnb = (ww & 3) * 32;
    const int nw = n0 + wnb;
    const int p = nw >> 6, tbase = nw & 63;  // 32-chunk stays in one t-block
    for (int half = 0; half < 2; ++half) {
        float* Cs = stage_cs_half(sm, acc, half);
#pragma unroll 4
        for (int mr = 0; mr < 32; ++mr) {
            const int oc = wmb + half * 32 + mr;
            const int h = oc >> 5, d = oc & 31;
            dst[((size_t)(b * NH + h) * NP + p) * NDT + d * 64 + tbase + lane] =
                Cs[lane * 33 + mr] + bias[oc];
        }
    }
}

// ---------------------------------------------------------------------------
// Kernel 2: energy E'[z][q][p] = sum_dt Q[q,dt] * K[p,dt]. grid(8, 4, 32).
// ---------------------------------------------------------------------------
__global__ void __launch_bounds__(512) energy_tc() {
    extern __shared__ float sm[];
    const int tid = threadIdx.x, lane = tid & 31, ww = tid >> 5;
    const int z = blockIdx.z;
    const int m0 = blockIdx.y * 256;   // q
    const int n0 = blockIdx.x * 128;   // p

    float acc[4][4][4];
    run_gemm<0, 0>(sm, g_qbuf + (size_t)z * NP * NDT + (size_t)m0 * NDT, NDT,
                   nullptr,
                   g_kbuf + (size_t)z * NP * NDT + (size_t)n0 * NDT, NDT,
                   NDT / 16, acc);

    const int wmb = (ww >> 2) * 64, wnb = (ww & 3) * 32;
    float* e = g_ebuf + (size_t)z * NP * NP + n0 + wnb + lane;
    for (int half = 0; half < 2; ++half) {
        float* Cs = stage_cs_half(sm, acc, half);
#pragma unroll 4
        for (int mr = 0; mr < 32; ++mr) {
            const int q = m0 + wmb + half * 32 + mr;
            e[(size_t)q * NP] = Cs[lane * 33 + mr];
        }
    }
}

// ---------------------------------------------------------------------------
// Kernel 3: softmax over q (unnormalized): e <- exp(e/sqrt(2048)),
// invS[z][p] = 1/sum_q. Logits are O(1) -> no max subtraction needed.
// ---------------------------------------------------------------------------
__global__ void __launch_bounds__(256) softmax_tc() {
    const int z = blockIdx.y;
    const int p = blockIdx.x * 256 + threadIdx.x;
    float* e = g_ebuf + (size_t)z * NP * NP + p;
    const float is = 0.022097086912079608f;  // 1/sqrt(2048)
    float s = 0.0f;
    for (int q = 0; q < NP; q += 4) {
        float v0 = e[(size_t)(q + 0) * NP];
        float v1 = e[(size_t)(q + 1) * NP];
        float v2 = e[(size_t)(q + 2) * NP];
        float v3 = e[(size_t)(q + 3) * NP];
        v0 = __expf(v0 * is); v1 = __expf(v1 * is);
        v2 = __expf(v2 * is); v3 = __expf(v3 * is);
        e[(size_t)(q + 0) * NP] = v0;
        e[(size_t)(q + 1) * NP] = v1;
        e[(size_t)(q + 2) * NP] = v2;
        e[(size_t)(q + 3) * NP] = v3;
        s += (v0 + v1) + (v2 + v3);
    }
    g_sbuf[(size_t)z * NP + p] = 1.0f / s;
}

// ---------------------------------------------------------------------------
// Kernel 4: AV. O[q][dt] = sum_p (attn'[q][p]*invS[p]) * V[p][dt].
// A = ebuf (k=p contiguous) scaled by invS; B = V via XT loader
// (B[n=dt][k=p] = V[p][dt]). grid(16, 4, 32): dt-tile, q-tile, z.
// Writes out[b][h*32+d][q][t], coalesced (lanes along t).
// ---------------------------------------------------------------------------
__global__ void __launch_bounds__(512) av_tc(float* __restrict__ out) {
    extern __shared__ float sm[];
    const int tid = threadIdx.x, lane = tid & 31, ww = tid >> 5;
    const int z = blockIdx.z, b = z >> 3, h = z & 7;
    const int m0 = blockIdx.y * 256;  // q
    const int n0 = blockIdx.x * 128;  // dt

    float acc[4][4][4];
    run_gemm<1, 1>(sm, g_ebuf + (size_t)z * NP * NP + (size_t)m0 * NP, NP,
                   g_sbuf + (size_t)z * NP,
                   g_vbuf + (size_t)z * NP * NDT + n0, NDT,
                   NP / 16, acc);

    const int wmb = (ww >> 2) * 64, wnb = (ww & 3) * 32;
    const int dtb = n0 + wnb;               // multiple of 32
    const int d = dtb >> 6, tbase = dtb & 63;
    float* ob = out + ((size_t)(b * NC) + h * ND + d) * NP * NT + tbase;
    for (int half = 0; half < 2; ++half) {
        float* Cs = stage_cs_half(sm, acc, half);
#pragma unroll 4
        for (int mr = 0; mr < 32; ++mr) {
            const int q = m0 + wmb + half * 32 + mr;
            ob[(size_t)q * NT + lane] = Cs[lane * 33 + mr];
        }
    }
}

// ---------------------------------------------------------------------------
extern "C" void kernel_launch(void* const* d_in, const int* in_sizes, int n_in,
                              void* d_out, int out_size) {
    const float* x  = (const float*)d_in[0];
    const float* Wk = (const float*)d_in[1];
    const float* bk = (const float*)d_in[2];
    const float* Wq = (const float*)d_in[3];
    const float* bq = (const float*)d_in[4];
    const float* Wv = (const float*)d_in[5];
    const float* bv = (const float*)d_in[6];
    float* out = (float*)d_out;

    cudaFuncSetAttribute(proj_tc, cudaFuncAttributeMaxDynamicSharedMemorySize, SMEM_SZ);
    cudaFuncSetAttribute(energy_tc, cudaFuncAttributeMaxDynamicSharedMemorySize, SMEM_SZ);
    cudaFuncSetAttribute(av_tc, cudaFuncAttributeMaxDynamicSharedMemorySize, SMEM_SZ);

    proj_tc<<<dim3(NPT / 128, 3, NB), 512, SMEM_SZ>>>(x, Wk, bk, Wq, bq, Wv, bv);
    energy_tc<<<dim3(NP / 128, NP / 256, NB * NH), 512, SMEM_SZ>>>();
    softmax_tc<<<dim3(NP / 256, NB * NH), 256>>>();
    av_tc<<<dim3(NDT / 128, NP / 256, NB * NH), 512, SMEM_SZ>>>(out);
}

// round 8
// speedup vs baseline: 2.4958x; 1.0573x over previous
#include <cuda_runtime.h>
#include <cstdint>

// B=4, C=256, P=1024, T=64, H=8, D=32, DT=2048
#define NB 4
#define NC 256
#define NP 1024
#define NT 64
#define NH 8
#define ND 32
#define NDT 2048
#define NPT 65536

// Scratch (__device__ globals per allocation-free rule)
__device__ float g_kbuf[(size_t)NB * NH * NP * NDT];   // [z][p][d*64+t]  (tf32-rounded)
__device__ float g_qbuf[(size_t)NB * NH * NP * NDT];   // [z][q][d*64+t]  (tf32-rounded)
__device__ float g_vbuf[(size_t)NB * NH * NP * NDT];   // [z][p][d*64+t]  (tf32-rounded)
__device__ float g_ebuf[(size_t)NB * NH * NP * NP];    // [z][q][p] E' -> attn (tf32) in place

// ---- proj (LDG/STS fragment-packed) staging, as in R7 ----
#define A_STRIDE 136
#define B_STRIDE 72
#define B_BASE   (32 * A_STRIDE)
#define STAGE_F  (B_BASE + 32 * B_STRIDE)      // 6656 floats/stage, 2 stages

// ---- cp.async natural-layout staging (energy/av) ----
#define APITCH 20                               // 16 + 4 pad floats
#define AF (256 * APITCH)                       // 5120 floats
#define BF (128 * APITCH)                       // 2560 floats
#define STAGE2 (AF + BF)                        // 7680 floats/stage
#define NSTG 4
#define CS_F (16 * 32 * 33)                     // epilogue staging, 16 warps
#define SMEM_SZ (NSTG * STAGE2 * 4)             // 122880 B (> 2*STAGE_F*4, > CS_F*4)

__device__ __forceinline__ int swsl(int l) { return l ^ (l >> 3); }

__device__ __forceinline__ float tf32r(float x) {
    uint32_t o;
    asm("cvt.rna.tf32.f32 %0, %1;" : "=r"(o) : "f"(x));
    return __uint_as_float(o);
}

__device__ __forceinline__ void cp16(void* dst, const void* src) {
    asm volatile("cp.async.cg.shared.global [%0], [%1], 16;"
                 :: "r"((uint32_t)__cvta_generic_to_shared(dst)), "l"(src));
}
__device__ __forceinline__ void cp4(void* dst, const void* src) {
    asm volatile("cp.async.ca.shared.global [%0], [%1], 4;"
                 :: "r"((uint32_t)__cvta_generic_to_shared(dst)), "l"(src));
}
#define CP_COMMIT() asm volatile("cp.async.commit_group;" ::: "memory")
#define CP_WAIT2()  asm volatile("cp.async.wait_group 2;" ::: "memory")

#define MMA8(c, a, b) asm volatile( \
    "mma.sync.aligned.m16n8k8.row.col.f32.tf32.tf32.f32 " \
    "{%0,%1,%2,%3}, {%4,%5,%6,%7}, {%8,%9}, {%0,%1,%2,%3};" \
    : "+f"((c)[0]), "+f"((c)[1]), "+f"((c)[2]), "+f"((c)[3]) \
    : "r"((a)[0]), "r"((a)[1]), "r"((a)[2]), "r"((a)[3]), \
      "r"((b)[0]), "r"((b)[1]))

// ---------------------------------------------------------------------------
// cp.async 4-stage mainloop: acc += A[256m x K] . B[128n x K]^T (NT), tf32.
// Operands MUST already be tf32-rounded in global memory (HW truncation is
// then exact). A k-contiguous. If XT: logical B[n][k] = Bg[k*ldb + n].
// CTA 256x128, BK=16, 16 warps (4m x 4n), warp tile 64m x 32n.
// ---------------------------------------------------------------------------
template <int XT>
__device__ __forceinline__ void run_gemm_ca(float* sm, const float* __restrict__ Ag,
                                            size_t lda, const float* __restrict__ Bg,
                                            size_t ldb, int nk, float acc[4][4][4]) {
    const int tid = threadIdx.x, lane = tid & 31, ww = tid >> 5;
    const int wmb = (ww >> 2) * 64, wnb = (ww & 3) * 32;
    const int g = lane >> 2, q = lane & 3;
    const int ar0 = tid >> 2, aqd = tid & 3;       // A/B(direct) ldg mapping
    const int xn = tid & 127, xkh = tid >> 7;      // B XT mapping

#pragma unroll
    for (int i = 0; i < 4; ++i)
#pragma unroll
        for (int j = 0; j < 4; ++j)
#pragma unroll
            for (int r = 0; r < 4; ++r) acc[i][j][r] = 0.0f;

#define ISSUE(c, s)                                                            \
    {                                                                          \
        float* sA = sm + (s) * STAGE2;                                         \
        float* sB = sA + AF;                                                   \
        const float* ap = Ag + (size_t)(c) * 16;                               \
        cp16(sA + ar0 * APITCH + aqd * 4, ap + (size_t)ar0 * lda + aqd * 4);   \
        cp16(sA + (ar0 + 128) * APITCH + aqd * 4,                              \
             ap + (size_t)(ar0 + 128) * lda + aqd * 4);                        \
        if (XT) {                                                              \
            const float* bp = Bg + (size_t)((c) * 16 + xkh * 4) * ldb + xn;    \
            float* bd = sB + xn * APITCH + xkh * 4;                            \
            cp4(bd + 0, bp);                                                   \
            cp4(bd + 1, bp + ldb);                                             \
            cp4(bd + 2, bp + 2 * ldb);                                         \
            cp4(bd + 3, bp + 3 * ldb);                                         \
        } else {                                                               \
            cp16(sB + ar0 * APITCH + aqd * 4,                                  \
                 Bg + (size_t)ar0 * ldb + (c) * 16 + aqd * 4);                 \
        }                                                                      \
    }

    for (int s = 0; s < NSTG - 1; ++s) {   // prologue: 3 stages in flight
        ISSUE(s, s);
        CP_COMMIT();
    }

    for (int c = 0; c < nk; ++c) {
        CP_WAIT2();          // stage c landed
        __syncthreads();     // everyone done reading stage (c-1)%4
        if (c + NSTG - 1 < nk) ISSUE(c + NSTG - 1, (c + NSTG - 1) & (NSTG - 1));
        CP_COMMIT();         // uniform group accounting (may be empty)

        const float* sa = sm + (c & (NSTG - 1)) * STAGE2;
        const float* sb = sa + AF;
#pragma unroll
        for (int kb = 0; kb < 2; ++kb) {
            const int kc = kb * 8 + q;
            uint32_t af[4][4], bf[4][2];
#pragma unroll
            for (int i = 0; i < 4; ++i) {
                const float* pa = sa + (wmb + i * 16 + g) * APITCH + kc;
                af[i][0] = *(const uint32_t*)(pa);
                af[i][1] = *(const uint32_t*)(pa + 8 * APITCH);
                af[i][2] = *(const uint32_t*)(pa + 4);
                af[i][3] = *(const uint32_t*)(pa + 8 * APITCH + 4);
            }
#pragma unroll
            for (int j = 0; j < 4; ++j) {
                const float* pb = sb + (wnb + j * 8 + g) * APITCH + kc;
                bf[j][0] = *(const uint32_t*)(pb);
                bf[j][1] = *(const uint32_t*)(pb + 4);
            }
#pragma unroll
            for (int i = 0; i < 4; ++i)
#pragma unroll
                for (int j = 0; j < 4; ++j) MMA8(acc[i][j], af[i], bf[j]);
        }
    }
    __syncthreads();
#undef ISSUE
}

// ---------------------------------------------------------------------------
// proj mainloop (R7's proven LDG->cvt->STS path, XT only). BK=16, 2 stages.
// ---------------------------------------------------------------------------
__device__ __forceinline__ void run_gemm_proj(float* sm, const float* __restrict__ Ag,
                                              size_t lda, const float* __restrict__ Bg,
                                              size_t ldb, int nk, float acc[4][4][4]) {
    const int tid = threadIdx.x, lane = tid & 31, ww = tid >> 5;
    const int wmi = (ww >> 2) * 4;
    const int wni = (ww & 3) * 4;

#pragma unroll
    for (int i = 0; i < 4; ++i)
#pragma unroll
        for (int j = 0; j < 4; ++j)
#pragma unroll
            for (int r = 0; r < 4; ++r) acc[i][j][r] = 0.0f;

    const int ar0 = tid >> 2, aqd = tid & 3;
    const int xn = tid & 127, xkh = tid >> 7;

    float4 va[2];
    float rx[4];

#define LDG_AB(c)                                                              \
    {                                                                          \
        const float* ap = Ag + (size_t)(c) * 16;                               \
        va[0] = *(const float4*)(ap + (size_t)ar0 * lda + aqd * 4);            \
        va[1] = *(const float4*)(ap + (size_t)(ar0 + 128) * lda + aqd * 4);    \
        const float* bp = Bg + (size_t)((c) * 16 + xkh * 4) * ldb + xn;        \
        _Pragma("unroll") for (int j = 0; j < 4; ++j)                          \
            rx[j] = bp[(size_t)j * ldb];                                       \
    }

#define STS_AB(st)                                                             \
    {                                                                          \
        float* stg = sm + (st) * STAGE_F;                                      \
        _Pragma("unroll") for (int i = 0; i < 2; ++i)                          \
        {                                                                      \
            int r = ar0 + i * 128;                                             \
            int mb = r >> 4, rr = r & 15, gg = rr & 7, mh = rr >> 3;           \
            int kb = aqd >> 1, ch = aqd & 1;                                   \
            float* ba = stg + (mb * 2 + kb) * A_STRIDE + mh + 2 * ch;          \
            ba[swsl(gg * 4 + 0) * 4] = tf32r(va[i].x);                         \
            ba[swsl(gg * 4 + 1) * 4] = tf32r(va[i].y);                         \
            ba[swsl(gg * 4 + 2) * 4] = tf32r(va[i].z);                         \
            ba[swsl(gg * 4 + 3) * 4] = tf32r(va[i].w);                         \
        }                                                                      \
        int nb = xn >> 3, gg = xn & 7;                                         \
        int kb = xkh >> 1, kh = xkh & 1;                                       \
        float* bb = stg + B_BASE + (nb * 2 + kb) * B_STRIDE + kh;              \
        _Pragma("unroll") for (int j = 0; j < 4; ++j)                          \
            bb[swsl(gg * 4 + j) * 2] = tf32r(rx[j]);                           \
    }

    LDG_AB(0);
    STS_AB(0);
    __syncthreads();

    const int sla = swsl(lane) * 4;
    const int slb = swsl(lane) * 2;

    for (int c = 0; c < nk; ++c) {
        if (c + 1 < nk) LDG_AB(c + 1);

        const float* sa = sm + (c & 1) * STAGE_F;
        const float* sb = sa + B_BASE;
        uint32_t af[4][4], bf[4][2];
#pragma unroll
        for (int kb = 0; kb < 2; ++kb) {
#pragma unroll
            for (int i = 0; i < 4; ++i) {
                uint4 u = *(const uint4*)(sa + ((wmi + i) * 2 + kb) * A_STRIDE + sla);
                af[i][0] = u.x; af[i][1] = u.y; af[i][2] = u.z; af[i][3] = u.w;
            }
#pragma unroll
            for (int i = 0; i < 4; ++i) {
                uint2 u = *(const uint2*)(sb + ((wni + i) * 2 + kb) * B_STRIDE + slb);
                bf[i][0] = u.x; bf[i][1] = u.y;
            }
#pragma unroll
            for (int i = 0; i < 4; ++i)
#pragma unroll
                for (int j = 0; j < 4; ++j) MMA8(acc[i][j], af[i], bf[j]);
        }
        if (c + 1 < nk) STS_AB((c + 1) & 1);
        __syncthreads();
    }
#undef LDG_AB
#undef STS_AB
}

// Stage one 32-row m-half of warp accumulators into Cs[n(32)][m(32)+pad].
__device__ __forceinline__ float* stage_cs_half(float* sm, float acc[4][4][4],
                                                int half) {
    const int tid = threadIdx.x, lane = tid & 31, ww = tid >> 5;
    float* Cs = sm + ww * (32 * 33);
    const int g = lane >> 2, q = lane & 3;
    __syncwarp();
#pragma unroll
    for (int i = 0; i < 2; ++i) {
        const int i2 = half * 2 + i;
#pragma unroll
        for (int j = 0; j < 4; ++j) {
            float* cp = Cs + (j * 8 + q * 2) * 33 + i * 16 + g;
            cp[0] = acc[i2][j][0];
            cp[33] = acc[i2][j][1];
            cp[8] = acc[i2][j][2];
            cp[33 + 8] = acc[i2][j][3];
        }
    }
    __syncwarp();
    return Cs;
}

// ---------------------------------------------------------------------------
// Kernel 1: QKV projection. grid(512, 3, 4). Outputs tf32-rounded.
// ---------------------------------------------------------------------------
__global__ void __launch_bounds__(512) proj_tc(
    const float* __restrict__ x,
    const float* __restrict__ Wk, const float* __restrict__ bk,
    const float* __restrict__ Wq, const float* __restrict__ bq,
    const float* __restrict__ Wv, const float* __restrict__ bv) {
    extern __shared__ float sm[];
    const int tid = threadIdx.x, lane = tid & 31, ww = tid >> 5;
    const int w = blockIdx.y, b = blockIdx.z;
    const int n0 = blockIdx.x * 128;

    const float* W    = (w == 0) ? Wk : (w == 1) ? Wq : Wv;
    const float* bias = (w == 0) ? bk : (w == 1) ? bq : bv;
    float* dst        = (w == 0) ? g_kbuf : (w == 1) ? g_qbuf : g_vbuf;

    float acc[4][4][4];
    run_gemm_proj(sm, W, NC, x + (size_t)b * NC * NPT + n0, NPT, NC / 16, acc);

    const int wmb = (ww >> 2) * 64, wnb = (ww & 3) * 32;
    const int nw = n0 + wnb;
    const int p = nw >> 6, tbase = nw & 63;
    for (int half = 0; half < 2; ++half) {
        float* Cs = stage_cs_half(sm, acc, half);
#pragma unroll 4
        for (int mr = 0; mr < 32; ++mr) {
            const int oc = wmb + half * 32 + mr;
            const int h = oc >> 5, d = oc & 31;
            dst[((size_t)(b * NH + h) * NP + p) * NDT + d * 64 + tbase + lane] =
                tf32r(Cs[lane * 33 + mr] + bias[oc]);
        }
    }
}

// ---------------------------------------------------------------------------
// Kernel 2: energy E'[z][q][p] = sum_dt Q[q,dt]*K[p,dt]. grid(8, 4, 32).
// ---------------------------------------------------------------------------
__global__ void __launch_bounds__(512) energy_tc() {
    extern __shared__ float sm[];
    const int tid = threadIdx.x, lane = tid & 31, ww = tid >> 5;
    const int z = blockIdx.z;
    const int m0 = blockIdx.y * 256;   // q
    const int n0 = blockIdx.x * 128;   // p

    float acc[4][4][4];
    run_gemm_ca<0>(sm, g_qbuf + (size_t)z * NP * NDT + (size_t)m0 * NDT, NDT,
                   g_kbuf + (size_t)z * NP * NDT + (size_t)n0 * NDT, NDT,
                   NDT / 16, acc);

    const int wmb = (ww >> 2) * 64, wnb = (ww & 3) * 32;
    float* e = g_ebuf + (size_t)z * NP * NP + n0 + wnb + lane;
    for (int half = 0; half < 2; ++half) {
        float* Cs = stage_cs_half(sm, acc, half);
#pragma unroll 4
        for (int mr = 0; mr < 32; ++mr) {
            const int q = m0 + wmb + half * 32 + mr;
            e[(size_t)q * NP] = Cs[lane * 33 + mr];
        }
    }
}

// ---------------------------------------------------------------------------
// Kernel 3: softmax over q, fully normalized + tf32-rounded in place.
// Pass 1: e <- exp(e/sqrt(2048)), accumulate column sum s.
// Pass 2: e <- tf32(e / s).  Thread owns column p -> no inter-thread sync.
// ---------------------------------------------------------------------------
__global__ void __launch_bounds__(256) softmax_tc() {
    const int z = blockIdx.y;
    const int p = blockIdx.x * 256 + threadIdx.x;
    float* e = g_ebuf + (size_t)z * NP * NP + p;
    const float is = 0.022097086912079608f;  // 1/sqrt(2048)
    float s = 0.0f;
    for (int q = 0; q < NP; q += 4) {
        float v0 = __expf(e[(size_t)(q + 0) * NP] * is);
        float v1 = __expf(e[(size_t)(q + 1) * NP] * is);
        float v2 = __expf(e[(size_t)(q + 2) * NP] * is);
        float v3 = __expf(e[(size_t)(q + 3) * NP] * is);
        e[(size_t)(q + 0) * NP] = v0;
        e[(size_t)(q + 1) * NP] = v1;
        e[(size_t)(q + 2) * NP] = v2;
        e[(size_t)(q + 3) * NP] = v3;
        s += (v0 + v1) + (v2 + v3);
    }
    const float inv = 1.0f / s;
    for (int q = 0; q < NP; q += 4) {
        e[(size_t)(q + 0) * NP] = tf32r(e[(size_t)(q + 0) * NP] * inv);
        e[(size_t)(q + 1) * NP] = tf32r(e[(size_t)(q + 1) * NP] * inv);
        e[(size_t)(q + 2) * NP] = tf32r(e[(size_t)(q + 2) * NP] * inv);
        e[(size_t)(q + 3) * NP] = tf32r(e[(size_t)(q + 3) * NP] * inv);
    }
}

// ---------------------------------------------------------------------------
// Kernel 4: AV. O[q][dt] = sum_p attn[q][p] * V[p][dt]. grid(16, 4, 32).
// A = ebuf (k=p contiguous); B = V via XT (B[n=dt][k=p] = V[p][dt]).
// ---------------------------------------------------------------------------
__global__ void __launch_bounds__(512) av_tc(float* __restrict__ out) {
    extern __shared__ float sm[];
    const int tid = threadIdx.x, lane = tid & 31, ww = tid >> 5;
    const int z = blockIdx.z, b = z >> 3, h = z & 7;
    const int m0 = blockIdx.y * 256;  // q
    const int n0 = blockIdx.x * 128;  // dt

    float acc[4][4][4];
    run_gemm_ca<1>(sm, g_ebuf + (size_t)z * NP * NP + (size_t)m0 * NP, NP,
                   g_vbuf + (size_t)z * NP * NDT + n0, NDT, NP / 16, acc);

    const int wmb = (ww >> 2) * 64, wnb = (ww & 3) * 32;
    const int dtb = n0 + wnb;
    const int d = dtb >> 6, tbase = dtb & 63;
    float* ob = out + ((size_t)(b * NC) + h * ND + d) * NP * NT + tbase;
    for (int half = 0; half < 2; ++half) {
        float* Cs = stage_cs_half(sm, acc, half);
#pragma unroll 4
        for (int mr = 0; mr < 32; ++mr) {
            const int q = m0 + wmb + half * 32 + mr;
            ob[(size_t)q * NT + lane] = Cs[lane * 33 + mr];
        }
    }
}

// ---------------------------------------------------------------------------
extern "C" void kernel_launch(void* const* d_in, const int* in_sizes, int n_in,
                              void* d_out, int out_size) {
    const float* x  = (const float*)d_in[0];
    const float* Wk = (const float*)d_in[1];
    const float* bk = (const float*)d_in[2];
    const float* Wq = (const float*)d_in[3];
    const float* bq = (const float*)d_in[4];
    const float* Wv = (const float*)d_in[5];
    const float* bv = (const float*)d_in[6];
    float* out = (float*)d_out;

    cudaFuncSetAttribute(proj_tc, cudaFuncAttributeMaxDynamicSharedMemorySize, SMEM_SZ);
    cudaFuncSetAttribute(energy_tc, cudaFuncAttributeMaxDynamicSharedMemorySize, SMEM_SZ);
    cudaFuncSetAttribute(av_tc, cudaFuncAttributeMaxDynamicSharedMemorySize, SMEM_SZ);

    proj_tc<<<dim3(NPT / 128, 3, NB), 512, SMEM_SZ>>>(x, Wk, bk, Wq, bq, Wv, bv);
    energy_tc<<<dim3(NP / 128, NP / 256, NB * NH), 512, SMEM_SZ>>>();
    softmax_tc<<<dim3(NP / 256, NB * NH), 256>>>();
    av_tc<<<dim3(NDT / 128, NP / 256, NB * NH), 512, SMEM_SZ>>>(out);
}

// round 9
// speedup vs baseline: 2.8023x; 1.1228x over previous
#include <cuda_runtime.h>
#include <cstdint>

// B=4, C=256, P=1024, T=64, H=8, D=32, DT=2048
#define NB 4
#define NC 256
#define NP 1024
#define NT 64
#define NH 8
#define ND 32
#define NDT 2048
#define NPT 65536

// Scratch (__device__ globals per allocation-free rule)
__device__ float g_kbuf[(size_t)NB * NH * NP * NDT];   // [z][p][d*64+t]  tf32
__device__ float g_qbuf[(size_t)NB * NH * NP * NDT];   // [z][q][d*64+t]  tf32
__device__ float g_vbuf[(size_t)NB * NH * NP * NDT];   // [z][p][d*64+t]  tf32
__device__ float g_vtbuf[(size_t)NB * NH * NDT * NP];  // [z][dt][p] = v*invS, tf32
__device__ float g_ebuf[(size_t)NB * NH * NP * NP];    // [z][q][p] E' -> exp (tf32)
__device__ float g_sbuf[(size_t)NB * NH * NP];         // invS per (z, p)

// ---- proj (LDG/STS fragment-packed) staging, as in R8 ----
#define A_STRIDE 136
#define B_STRIDE 72
#define B_BASE   (32 * A_STRIDE)
#define STAGE_F  (B_BASE + 32 * B_STRIDE)      // 6656 floats/stage, 2 stages
#define SMEM_PROJ (16 * 32 * 33 * 4)           // 67584 B (>= 2*STAGE_F*4 = 53248)

// ---- cp.async natural staging for energy/av: tile 128x128, BK=32 ----
#define APITCH 36                               // 32 + 4 pad floats
#define AFL (128 * APITCH)                      // 4608 floats
#define STG2 (2 * AFL)                          // 9216 floats/stage
#define NST 3
#define SMEM_GEMM (NST * STG2 * 4)              // 110592 B -> 2 CTAs/SM

__device__ __forceinline__ int swsl(int l) { return l ^ (l >> 3); }

__device__ __forceinline__ float tf32r(float x) {
    uint32_t o;
    asm("cvt.rna.tf32.f32 %0, %1;" : "=r"(o) : "f"(x));
    return __uint_as_float(o);
}

__device__ __forceinline__ void cp16(void* dst, const void* src) {
    asm volatile("cp.async.cg.shared.global [%0], [%1], 16;"
                 :: "r"((uint32_t)__cvta_generic_to_shared(dst)), "l"(src));
}
#define CP_COMMIT() asm volatile("cp.async.commit_group;" ::: "memory")

#define MMA8(c, a, b) asm volatile( \
    "mma.sync.aligned.m16n8k8.row.col.f32.tf32.tf32.f32 " \
    "{%0,%1,%2,%3}, {%4,%5,%6,%7}, {%8,%9}, {%0,%1,%2,%3};" \
    : "+f"((c)[0]), "+f"((c)[1]), "+f"((c)[2]), "+f"((c)[3]) \
    : "r"((a)[0]), "r"((a)[1]), "r"((a)[2]), "r"((a)[3]), \
      "r"((b)[0]), "r"((b)[1]))

// ---------------------------------------------------------------------------
// cp.async 3-stage mainloop: acc += A[128m x K] . B[128n x K]^T (NT), tf32.
// Both operands k-contiguous, already tf32-rounded in gmem.
// CTA 128x128, BK=32, 8 warps (2m x 4n), warp tile 64m x 32n. 256 threads.
// ---------------------------------------------------------------------------
__device__ __forceinline__ void run_gemm_nn(float* sm, const float* __restrict__ Ag,
                                            size_t lda, const float* __restrict__ Bg,
                                            size_t ldb, int nk, float acc[4][4][4]) {
    const int tid = threadIdx.x, lane = tid & 31, ww = tid >> 5;
    const int wmb = (ww >> 2) * 64, wnb = (ww & 3) * 32;
    const int g = lane >> 2, q = lane & 3;
    const int lrow = tid >> 3, lq8 = (tid & 7) * 4;

#pragma unroll
    for (int i = 0; i < 4; ++i)
#pragma unroll
        for (int j = 0; j < 4; ++j)
#pragma unroll
            for (int r = 0; r < 4; ++r) acc[i][j][r] = 0.0f;

#define ISSUE(c, s)                                                            \
    {                                                                          \
        float* sA = sm + (s) * STG2;                                           \
        float* sB = sA + AFL;                                                  \
        _Pragma("unroll") for (int r = 0; r < 4; ++r)                          \
        {                                                                      \
            int row = r * 32 + lrow;                                           \
            cp16(sA + row * APITCH + lq8,                                      \
                 Ag + (size_t)row * lda + (c) * 32 + lq8);                     \
            cp16(sB + row * APITCH + lq8,                                      \
                 Bg + (size_t)row * ldb + (c) * 32 + lq8);                     \
        }                                                                      \
    }

    ISSUE(0, 0); CP_COMMIT();
    ISSUE(1, 1); CP_COMMIT();

    int s = 0;
    for (int c = 0; c < nk; ++c) {
        asm volatile("cp.async.wait_group 1;" ::: "memory");
        __syncthreads();
        if (c + 2 < nk) {
            int s2 = s + 2; if (s2 >= NST) s2 -= NST;
            ISSUE(c + 2, s2);
        }
        CP_COMMIT();

        const float* sa = sm + s * STG2;
        const float* sb = sa + AFL;
#pragma unroll
        for (int kb = 0; kb < 4; ++kb) {
            const int kc = kb * 8 + q;
            uint32_t af[4][4], bf[4][2];
#pragma unroll
            for (int i = 0; i < 4; ++i) {
                const float* pa = sa + (wmb + i * 16 + g) * APITCH + kc;
                af[i][0] = *(const uint32_t*)pa;
                af[i][1] = *(const uint32_t*)(pa + 8 * APITCH);
                af[i][2] = *(const uint32_t*)(pa + 4);
                af[i][3] = *(const uint32_t*)(pa + 8 * APITCH + 4);
            }
#pragma unroll
            for (int j = 0; j < 4; ++j) {
                const float* pb = sb + (wnb + j * 8 + g) * APITCH + kc;
                bf[j][0] = *(const uint32_t*)pb;
                bf[j][1] = *(const uint32_t*)(pb + 4);
            }
#pragma unroll
            for (int i = 0; i < 4; ++i)
#pragma unroll
                for (int j = 0; j < 4; ++j) MMA8(acc[i][j], af[i], bf[j]);
        }
        if (++s == NST) s = 0;
    }
    __syncthreads();   // before epilogue reuses staging smem
#undef ISSUE
}

// ---------------------------------------------------------------------------
// proj mainloop (R8's proven LDG->cvt->STS path, x-transpose). BK=16.
// CTA 256m x 128n, 512 threads, 16 warps.
// ---------------------------------------------------------------------------
__device__ __forceinline__ void run_gemm_proj(float* sm, const float* __restrict__ Ag,
                                              size_t lda, const float* __restrict__ Bg,
                                              size_t ldb, int nk, float acc[4][4][4]) {
    const int tid = threadIdx.x, lane = tid & 31, ww = tid >> 5;
    const int wmi = (ww >> 2) * 4;
    const int wni = (ww & 3) * 4;

#pragma unroll
    for (int i = 0; i < 4; ++i)
#pragma unroll
        for (int j = 0; j < 4; ++j)
#pragma unroll
            for (int r = 0; r < 4; ++r) acc[i][j][r] = 0.0f;

    const int ar0 = tid >> 2, aqd = tid & 3;
    const int xn = tid & 127, xkh = tid >> 7;

    float4 va[2];
    float rx[4];

#define LDG_AB(c)                                                              \
    {                                                                          \
        const float* ap = Ag + (size_t)(c) * 16;                               \
        va[0] = *(const float4*)(ap + (size_t)ar0 * lda + aqd * 4);            \
        va[1] = *(const float4*)(ap + (size_t)(ar0 + 128) * lda + aqd * 4);    \
        const float* bp = Bg + (size_t)((c) * 16 + xkh * 4) * ldb + xn;        \
        _Pragma("unroll") for (int j = 0; j < 4; ++j)                          \
            rx[j] = bp[(size_t)j * ldb];                                       \
    }

#define STS_AB(st)                                                             \
    {                                                                          \
        float* stg = sm + (st) * STAGE_F;                                      \
        _Pragma("unroll") for (int i = 0; i < 2; ++i)                          \
        {                                                                      \
            int r = ar0 + i * 128;                                             \
            int mb = r >> 4, rr = r & 15, gg = rr & 7, mh = rr >> 3;           \
            int kb = aqd >> 1, ch = aqd & 1;                                   \
            float* ba = stg + (mb * 2 + kb) * A_STRIDE + mh + 2 * ch;          \
            ba[swsl(gg * 4 + 0) * 4] = tf32r(va[i].x);                         \
            ba[swsl(gg * 4 + 1) * 4] = tf32r(va[i].y);                         \
            ba[swsl(gg * 4 + 2) * 4] = tf32r(va[i].z);                         \
            ba[swsl(gg * 4 + 3) * 4] = tf32r(va[i].w);                         \
        }                                                                      \
        int nb = xn >> 3, gg = xn & 7;                                         \
        int kb = xkh >> 1, kh = xkh & 1;                                       \
        float* bb = stg + B_BASE + (nb * 2 + kb) * B_STRIDE + kh;              \
        _Pragma("unroll") for (int j = 0; j < 4; ++j)                          \
            bb[swsl(gg * 4 + j) * 2] = tf32r(rx[j]);                           \
    }

    LDG_AB(0);
    STS_AB(0);
    __syncthreads();

    const int sla = swsl(lane) * 4;
    const int slb = swsl(lane) * 2;

    for (int c = 0; c < nk; ++c) {
        if (c + 1 < nk) LDG_AB(c + 1);

        const float* sa = sm + (c & 1) * STAGE_F;
        const float* sb = sa + B_BASE;
        uint32_t af[4][4], bf[4][2];
#pragma unroll
        for (int kb = 0; kb < 2; ++kb) {
#pragma unroll
            for (int i = 0; i < 4; ++i) {
                uint4 u = *(const uint4*)(sa + ((wmi + i) * 2 + kb) * A_STRIDE + sla);
                af[i][0] = u.x; af[i][1] = u.y; af[i][2] = u.z; af[i][3] = u.w;
            }
#pragma unroll
            for (int i = 0; i < 4; ++i) {
                uint2 u = *(const uint2*)(sb + ((wni + i) * 2 + kb) * B_STRIDE + slb);
                bf[i][0] = u.x; bf[i][1] = u.y;
            }
#pragma unroll
            for (int i = 0; i < 4; ++i)
#pragma unroll
                for (int j = 0; j < 4; ++j) MMA8(acc[i][j], af[i], bf[j]);
        }
        if (c + 1 < nk) STS_AB((c + 1) & 1);
        __syncthreads();
    }
#undef LDG_AB
#undef STS_AB
}

// Stage one 32-row m-half of warp accumulators into Cs[n(32)][m(32)+pad].
__device__ __forceinline__ float* stage_cs_half(float* sm, float acc[4][4][4],
                                                int half) {
    const int tid = threadIdx.x, lane = tid & 31, ww = tid >> 5;
    float* Cs = sm + ww * (32 * 33);
    const int g = lane >> 2, q = lane & 3;
    __syncwarp();
#pragma unroll
    for (int i = 0; i < 2; ++i) {
        const int i2 = half * 2 + i;
#pragma unroll
        for (int j = 0; j < 4; ++j) {
            float* cp = Cs + (j * 8 + q * 2) * 33 + i * 16 + g;
            cp[0] = acc[i2][j][0];
            cp[33] = acc[i2][j][1];
            cp[8] = acc[i2][j][2];
            cp[33 + 8] = acc[i2][j][3];
        }
    }
    __syncwarp();
    return Cs;
}

// ---------------------------------------------------------------------------
// Kernel 1: QKV projection. grid(512, 3, 4). Outputs tf32-rounded.
// ---------------------------------------------------------------------------
__global__ void __launch_bounds__(512) proj_tc(
    const float* __restrict__ x,
    const float* __restrict__ Wk, const float* __restrict__ bk,
    const float* __restrict__ Wq, const float* __restrict__ bq,
    const float* __restrict__ Wv, const float* __restrict__ bv) {
    extern __shared__ float sm[];
    const int tid = threadIdx.x, lane = tid & 31, ww = tid >> 5;
    const int w = blockIdx.y, b = blockIdx.z;
    const int n0 = blockIdx.x * 128;

    const float* W    = (w == 0) ? Wk : (w == 1) ? Wq : Wv;
    const float* bias = (w == 0) ? bk : (w == 1) ? bq : bv;
    float* dst        = (w == 0) ? g_kbuf : (w == 1) ? g_qbuf : g_vbuf;

    float acc[4][4][4];
    run_gemm_proj(sm, W, NC, x + (size_t)b * NC * NPT + n0, NPT, NC / 16, acc);

    const int wmb = (ww >> 2) * 64, wnb = (ww & 3) * 32;
    const int nw = n0 + wnb;
    const int p = nw >> 6, tbase = nw & 63;
    for (int half = 0; half < 2; ++half) {
        float* Cs = stage_cs_half(sm, acc, half);
#pragma unroll 4
        for (int mr = 0; mr < 32; ++mr) {
            const int oc = wmb + half * 32 + mr;
            const int h = oc >> 5, d = oc & 31;
            dst[((size_t)(b * NH + h) * NP + p) * NDT + d * 64 + tbase + lane] =
                tf32r(Cs[lane * 33 + mr] + bias[oc]);
        }
    }
}

// ---------------------------------------------------------------------------
// Kernel 2: energy E'[z][q][p] = sum_dt Q[q,dt]*K[p,dt]. grid(8, 8, 32).
// ---------------------------------------------------------------------------
__global__ void __launch_bounds__(256, 2) energy_tc() {
    extern __shared__ float sm[];
    const int tid = threadIdx.x, lane = tid & 31, ww = tid >> 5;
    const int z = blockIdx.z;
    const int m0 = blockIdx.y * 128;   // q
    const int n0 = blockIdx.x * 128;   // p

    float acc[4][4][4];
    run_gemm_nn(sm, g_qbuf + (size_t)z * NP * NDT + (size_t)m0 * NDT, NDT,
                g_kbuf + (size_t)z * NP * NDT + (size_t)n0 * NDT, NDT,
                NDT / 32, acc);

    const int wmb = (ww >> 2) * 64, wnb = (ww & 3) * 32;
    float* e = g_ebuf + (size_t)z * NP * NP + n0 + wnb + lane;
    for (int half = 0; half < 2; ++half) {
        float* Cs = stage_cs_half(sm, acc, half);
#pragma unroll 4
        for (int mr = 0; mr < 32; ++mr) {
            const int q = m0 + wmb + half * 32 + mr;
            e[(size_t)q * NP] = Cs[lane * 33 + mr];
        }
    }
}

// ---------------------------------------------------------------------------
// Kernel 3: softmax over q. Pass 1: e <- exp(e/sqrt(2048)), invS = 1/sum.
// Pass 2: e <- tf32(e)  (normalization folded into vt).
// ---------------------------------------------------------------------------
__global__ void __launch_bounds__(256) softmax_tc() {
    const int z = blockIdx.y;
    const int p = blockIdx.x * 256 + threadIdx.x;
    float* e = g_ebuf + (size_t)z * NP * NP + p;
    const float is = 0.022097086912079608f;  // 1/sqrt(2048)
    float s = 0.0f;
    for (int q = 0; q < NP; q += 4) {
        float v0 = __expf(e[(size_t)(q + 0) * NP] * is);
        float v1 = __expf(e[(size_t)(q + 1) * NP] * is);
        float v2 = __expf(e[(size_t)(q + 2) * NP] * is);
        float v3 = __expf(e[(size_t)(q + 3) * NP] * is);
        e[(size_t)(q + 0) * NP] = tf32r(v0);
        e[(size_t)(q + 1) * NP] = tf32r(v1);
        e[(size_t)(q + 2) * NP] = tf32r(v2);
        e[(size_t)(q + 3) * NP] = tf32r(v3);
        s += (v0 + v1) + (v2 + v3);
    }
    g_sbuf[(size_t)z * NP + p] = 1.0f / s;
}

// ---------------------------------------------------------------------------
// Kernel 4: vt[z][dt][p] = tf32(v[z][p][dt] * invS[p]).  grid(32, 16, 32).
// ---------------------------------------------------------------------------
__global__ void __launch_bounds__(256) vtrans_tc() {
    __shared__ float ts[64][68];
    const int tid = threadIdx.x;
    const int z = blockIdx.z;
    const int dt0 = blockIdx.x * 64;
    const int p0 = blockIdx.y * 64;

    const float* in = g_vbuf + (size_t)z * NP * NDT;
    const float* invS = g_sbuf + (size_t)z * NP;
#pragma unroll
    for (int i = 0; i < 4; ++i) {
        int idx = i * 256 + tid;
        int r = idx >> 4, c4 = (idx & 15) * 4;
        float sc = invS[p0 + r];
        float4 v = *(const float4*)(in + (size_t)(p0 + r) * NDT + dt0 + c4);
        ts[r][c4 + 0] = tf32r(v.x * sc);
        ts[r][c4 + 1] = tf32r(v.y * sc);
        ts[r][c4 + 2] = tf32r(v.z * sc);
        ts[r][c4 + 3] = tf32r(v.w * sc);
    }
    __syncthreads();
    float* out = g_vtbuf + (size_t)z * NDT * NP;
#pragma unroll
    for (int i = 0; i < 4; ++i) {
        int idx = i * 256 + tid;
        int r = idx >> 4, c4 = (idx & 15) * 4;
        float4 w;
        w.x = ts[c4 + 0][r];
        w.y = ts[c4 + 1][r];
        w.z = ts[c4 + 2][r];
        w.w = ts[c4 + 3][r];
        *(float4*)(out + (size_t)(dt0 + r) * NP + p0 + c4) = w;
    }
}

// ---------------------------------------------------------------------------
// Kernel 5: AV. O'[dt][q] = sum_p vt[dt,p] * attn'[q,p]. grid(8, 16, 32).
// Both operands natural (k=p contiguous). Coalesced output (lanes along t).
// ---------------------------------------------------------------------------
__global__ void __launch_bounds__(256, 2) av_tc(float* __restrict__ out) {
    extern __shared__ float sm[];
    const int tid = threadIdx.x, lane = tid & 31, ww = tid >> 5;
    const int z = blockIdx.z, b = z >> 3, h = z & 7;
    const int m0 = blockIdx.y * 128;  // dt
    const int n0 = blockIdx.x * 128;  // q

    float acc[4][4][4];
    run_gemm_nn(sm, g_vtbuf + (size_t)z * NDT * NP + (size_t)m0 * NP, NP,
                g_ebuf + (size_t)z * NP * NP + (size_t)n0 * NP, NP,
                NP / 32, acc);

    const int wmb = (ww >> 2) * 64, wnb = (ww & 3) * 32;
    for (int half = 0; half < 2; ++half) {
        float* Cs = stage_cs_half(sm, acc, half);
        const int dtb = m0 + wmb + half * 32;   // 32 consecutive dt
        const int d = dtb >> 6, tbase = dtb & 63;
        float* ob = out + ((size_t)(b * NC) + h * ND + d) * NP * NT + tbase;
#pragma unroll 4
        for (int nn = 0; nn < 32; ++nn) {
            const int q = n0 + wnb + nn;
            ob[(size_t)q * NT + lane] = Cs[nn * 33 + lane];
        }
    }
}

// ---------------------------------------------------------------------------
extern "C" void kernel_launch(void* const* d_in, const int* in_sizes, int n_in,
                              void* d_out, int out_size) {
    const float* x  = (const float*)d_in[0];
    const float* Wk = (const float*)d_in[1];
    const float* bk = (const float*)d_in[2];
    const float* Wq = (const float*)d_in[3];
    const float* bq = (const float*)d_in[4];
    const float* Wv = (const float*)d_in[5];
    const float* bv = (const float*)d_in[6];
    float* out = (float*)d_out;

    cudaFuncSetAttribute(proj_tc, cudaFuncAttributeMaxDynamicSharedMemorySize, SMEM_PROJ);
    cudaFuncSetAttribute(energy_tc, cudaFuncAttributeMaxDynamicSharedMemorySize, SMEM_GEMM);
    cudaFuncSetAttribute(av_tc, cudaFuncAttributeMaxDynamicSharedMemorySize, SMEM_GEMM);

    proj_tc<<<dim3(NPT / 128, 3, NB), 512, SMEM_PROJ>>>(x, Wk, bk, Wq, bq, Wv, bv);
    energy_tc<<<dim3(NP / 128, NP / 128, NB * NH), 256, SMEM_GEMM>>>();
    softmax_tc<<<dim3(NP / 256, NB * NH), 256>>>();
    vtrans_tc<<<dim3(NDT / 64, NP / 64, NB * NH), 256>>>();
    av_tc<<<dim3(NP / 128, NDT / 128, NB * NH), 256, SMEM_GEMM>>>(out);
}

// round 10
// speedup vs baseline: 2.8812x; 1.0281x over previous
#include <cuda_runtime.h>
#include <cstdint>

// B=4, C=256, P=1024, T=64, H=8, D=32, DT=2048
#define NB 4
#define NC 256
#define NP 1024
#define NT 64
#define NH 8
#define ND 32
#define NDT 2048
#define NPT 65536

// Scratch (__device__ globals per allocation-free rule)
__device__ float g_kbuf[(size_t)NB * NH * NP * NDT];   // [z][p][d*64+t]  tf32
__device__ float g_qbuf[(size_t)NB * NH * NP * NDT];   // [z][q][d*64+t]  tf32
__device__ float g_vbuf[(size_t)NB * NH * NP * NDT];   // [z][p][d*64+t]  tf32
__device__ float g_vtbuf[(size_t)NB * NH * NDT * NP];  // [z][dt][p] = v*invS, tf32
__device__ float g_ebuf[(size_t)NB * NH * NP * NP];    // [z][q][p]  exp(E'/s), tf32
__device__ float g_sbuf[(size_t)NB * NH * NP];         // invS per (z, p)
__device__ float g_xtbuf[(size_t)NB * NPT * NC];       // [b][n][c] = tf32(x^T)
__device__ float g_wbuf[3 * NC * NC];                  // tf32-rounded Wk,Wq,Wv

// ---- cp.async natural staging: tile 128x128, BK=32, 3 stages ----
#define APITCH 36                               // 32 + 4 pad floats
#define AFL (128 * APITCH)                      // 4608 floats
#define STG2 (2 * AFL)                          // 9216 floats/stage
#define NST 3
#define SMEM_GEMM (NST * STG2 * 4)              // 110592 B -> 2 CTAs/SM

__device__ __forceinline__ float tf32r(float x) {
    uint32_t o;
    asm("cvt.rna.tf32.f32 %0, %1;" : "=r"(o) : "f"(x));
    return __uint_as_float(o);
}

__device__ __forceinline__ void cp16(void* dst, const void* src) {
    asm volatile("cp.async.cg.shared.global [%0], [%1], 16;"
                 :: "r"((uint32_t)__cvta_generic_to_shared(dst)), "l"(src));
}
#define CP_COMMIT() asm volatile("cp.async.commit_group;" ::: "memory")

#define MMA8(c, a, b) asm volatile( \
    "mma.sync.aligned.m16n8k8.row.col.f32.tf32.tf32.f32 " \
    "{%0,%1,%2,%3}, {%4,%5,%6,%7}, {%8,%9}, {%0,%1,%2,%3};" \
    : "+f"((c)[0]), "+f"((c)[1]), "+f"((c)[2]), "+f"((c)[3]) \
    : "r"((a)[0]), "r"((a)[1]), "r"((a)[2]), "r"((a)[3]), \
      "r"((b)[0]), "r"((b)[1]))

// ---------------------------------------------------------------------------
// cp.async 3-stage mainloop: acc += A[128m x K] . B[128n x K]^T (NT), tf32.
// Both operands k-contiguous, already tf32-rounded in gmem.
// CTA 128x128, BK=32, 8 warps (2m x 4n), warp tile 64m x 32n. 256 threads.
// ---------------------------------------------------------------------------
__device__ __forceinline__ void run_gemm_nn(float* sm, const float* __restrict__ Ag,
                                            size_t lda, const float* __restrict__ Bg,
                                            size_t ldb, int nk, float acc[4][4][4]) {
    const int tid = threadIdx.x, lane = tid & 31, ww = tid >> 5;
    const int wmb = (ww >> 2) * 64, wnb = (ww & 3) * 32;
    const int g = lane >> 2, q = lane & 3;
    const int lrow = tid >> 3, lq8 = (tid & 7) * 4;

#pragma unroll
    for (int i = 0; i < 4; ++i)
#pragma unroll
        for (int j = 0; j < 4; ++j)
#pragma unroll
            for (int r = 0; r < 4; ++r) acc[i][j][r] = 0.0f;

#define ISSUE(c, s)                                                            \
    {                                                                          \
        float* sA = sm + (s) * STG2;                                           \
        float* sB = sA + AFL;                                                  \
        _Pragma("unroll") for (int r = 0; r < 4; ++r)                          \
        {                                                                      \
            int row = r * 32 + lrow;                                           \
            cp16(sA + row * APITCH + lq8,                                      \
                 Ag + (size_t)row * lda + (c) * 32 + lq8);                     \
            cp16(sB + row * APITCH + lq8,                                      \
                 Bg + (size_t)row * ldb + (c) * 32 + lq8);                     \
        }                                                                      \
    }

    ISSUE(0, 0); CP_COMMIT();
    ISSUE(1, 1); CP_COMMIT();

    int s = 0;
    for (int c = 0; c < nk; ++c) {
        asm volatile("cp.async.wait_group 1;" ::: "memory");
        __syncthreads();
        if (c + 2 < nk) {
            int s2 = s + 2; if (s2 >= NST) s2 -= NST;
            ISSUE(c + 2, s2);
        }
        CP_COMMIT();

        const float* sa = sm + s * STG2;
        const float* sb = sa + AFL;
#pragma unroll
        for (int kb = 0; kb < 4; ++kb) {
            const int kc = kb * 8 + q;
            uint32_t af[4][4], bf[4][2];
#pragma unroll
            for (int i = 0; i < 4; ++i) {
                const float* pa = sa + (wmb + i * 16 + g) * APITCH + kc;
                af[i][0] = *(const uint32_t*)pa;
                af[i][1] = *(const uint32_t*)(pa + 8 * APITCH);
                af[i][2] = *(const uint32_t*)(pa + 4);
                af[i][3] = *(const uint32_t*)(pa + 8 * APITCH + 4);
            }
#pragma unroll
            for (int j = 0; j < 4; ++j) {
                const float* pb = sb + (wnb + j * 8 + g) * APITCH + kc;
                bf[j][0] = *(const uint32_t*)pb;
                bf[j][1] = *(const uint32_t*)(pb + 4);
            }
#pragma unroll
            for (int i = 0; i < 4; ++i)
#pragma unroll
                for (int j = 0; j < 4; ++j) MMA8(acc[i][j], af[i], bf[j]);
        }
        if (++s == NST) s = 0;
    }
    __syncthreads();   // before epilogue reuses staging smem
#undef ISSUE
}

// Stage one 32-row m-half of warp accumulators into Cs[n(32)][m(32)+pad].
__device__ __forceinline__ float* stage_cs_half(float* sm, float acc[4][4][4],
                                                int half) {
    const int tid = threadIdx.x, lane = tid & 31, ww = tid >> 5;
    float* Cs = sm + ww * (32 * 33);
    const int g = lane >> 2, q = lane & 3;
    __syncwarp();
#pragma unroll
    for (int i = 0; i < 2; ++i) {
        const int i2 = half * 2 + i;
#pragma unroll
        for (int j = 0; j < 4; ++j) {
            float* cp = Cs + (j * 8 + q * 2) * 33 + i * 16 + g;
            cp[0] = acc[i2][j][0];
            cp[33] = acc[i2][j][1];
            cp[8] = acc[i2][j][2];
            cp[33 + 8] = acc[i2][j][3];
        }
    }
    __syncwarp();
    return Cs;
}

// ---------------------------------------------------------------------------
// Kernel 0a: round W to tf32. grid(64, 3), 256 threads.
// ---------------------------------------------------------------------------
__global__ void __launch_bounds__(256) wround_tc(
    const float* __restrict__ Wk, const float* __restrict__ Wq,
    const float* __restrict__ Wv) {
    const int w = blockIdx.y;
    const float* W = (w == 0) ? Wk : (w == 1) ? Wq : Wv;
    float* dst = g_wbuf + w * NC * NC;
    const int base = blockIdx.x * 1024;
#pragma unroll
    for (int j = 0; j < 4; ++j) {
        int idx = base + j * 256 + threadIdx.x;
        dst[idx] = tf32r(W[idx]);
    }
}

// ---------------------------------------------------------------------------
// Kernel 0b: xt[b][n][c] = tf32(x[b][c][n]). grid(1024, 4, 4), 64x64 tiles.
// ---------------------------------------------------------------------------
__global__ void __launch_bounds__(256) xtrans_tc(const float* __restrict__ x) {
    __shared__ float ts[64][68];
    const int tid = threadIdx.x;
    const int n0 = blockIdx.x * 64;
    const int c0 = blockIdx.y * 64;
    const int b = blockIdx.z;

    const float* in = x + (size_t)b * NC * NPT;
#pragma unroll
    for (int i = 0; i < 4; ++i) {
        int idx = i * 256 + tid;
        int r = idx >> 4, c4 = (idx & 15) * 4;   // r = c row, c4 = n col
        float4 v = *(const float4*)(in + (size_t)(c0 + r) * NPT + n0 + c4);
        ts[r][c4 + 0] = tf32r(v.x);
        ts[r][c4 + 1] = tf32r(v.y);
        ts[r][c4 + 2] = tf32r(v.z);
        ts[r][c4 + 3] = tf32r(v.w);
    }
    __syncthreads();
    float* out = g_xtbuf + (size_t)b * NPT * NC;
#pragma unroll
    for (int i = 0; i < 4; ++i) {
        int idx = i * 256 + tid;
        int r = idx >> 4, c4 = (idx & 15) * 4;   // r = n row, c4 = c col
        float4 w;
        w.x = ts[c4 + 0][r];
        w.y = ts[c4 + 1][r];
        w.z = ts[c4 + 2][r];
        w.w = ts[c4 + 3][r];
        *(float4*)(out + (size_t)(n0 + r) * NC + c0 + c4) = w;
    }
}

// ---------------------------------------------------------------------------
// Kernel 1: QKV projection via NN mainloop. grid(512, 6, 4): n-tile, w*2+mt, b.
// A = Wr[oc][c] (128-row tile), B = xt[n][c]. Outputs tf32-rounded.
// ---------------------------------------------------------------------------
__global__ void __launch_bounds__(256, 2) proj_tc(
    const float* __restrict__ bk, const float* __restrict__ bq,
    const float* __restrict__ bv) {
    extern __shared__ float sm[];
    const int tid = threadIdx.x, lane = tid & 31, ww = tid >> 5;
    const int w = blockIdx.y >> 1, mt = blockIdx.y & 1, b = blockIdx.z;
    const int n0 = blockIdx.x * 128;

    const float* bias = (w == 0) ? bk : (w == 1) ? bq : bv;
    float* dst        = (w == 0) ? g_kbuf : (w == 1) ? g_qbuf : g_vbuf;

    float acc[4][4][4];
    run_gemm_nn(sm, g_wbuf + (size_t)w * NC * NC + (size_t)(mt * 128) * NC, NC,
                g_xtbuf + (size_t)b * NPT * NC + (size_t)n0 * NC, NC,
                NC / 32, acc);

    const int wmb = (ww >> 2) * 64, wnb = (ww & 3) * 32;
    const int nw = n0 + wnb;
    const int p = nw >> 6, tbase = nw & 63;  // 32-lane chunk stays in one t-block
    for (int half = 0; half < 2; ++half) {
        float* Cs = stage_cs_half(sm, acc, half);
#pragma unroll 4
        for (int mr = 0; mr < 32; ++mr) {
            const int oc = mt * 128 + wmb + half * 32 + mr;
            const int h = oc >> 5, d = oc & 31;
            dst[((size_t)(b * NH + h) * NP + p) * NDT + d * 64 + tbase + lane] =
                tf32r(Cs[lane * 33 + mr] + bias[oc]);
        }
    }
}

// ---------------------------------------------------------------------------
// Kernel 2: energy + fused exp:  e'[z][q][p] = tf32(exp(QK/sqrt(2048))).
// grid(8, 8, 32).
// ---------------------------------------------------------------------------
__global__ void __launch_bounds__(256, 2) energy_tc() {
    extern __shared__ float sm[];
    const int tid = threadIdx.x, lane = tid & 31, ww = tid >> 5;
    const int z = blockIdx.z;
    const int m0 = blockIdx.y * 128;   // q
    const int n0 = blockIdx.x * 128;   // p

    float acc[4][4][4];
    run_gemm_nn(sm, g_qbuf + (size_t)z * NP * NDT + (size_t)m0 * NDT, NDT,
                g_kbuf + (size_t)z * NP * NDT + (size_t)n0 * NDT, NDT,
                NDT / 32, acc);

    const float is = 0.022097086912079608f;  // 1/sqrt(2048)
    const int wmb = (ww >> 2) * 64, wnb = (ww & 3) * 32;
    float* e = g_ebuf + (size_t)z * NP * NP + n0 + wnb + lane;
    for (int half = 0; half < 2; ++half) {
        float* Cs = stage_cs_half(sm, acc, half);
#pragma unroll 4
        for (int mr = 0; mr < 32; ++mr) {
            const int q = m0 + wmb + half * 32 + mr;
            e[(size_t)q * NP] = tf32r(__expf(Cs[lane * 33 + mr] * is));
        }
    }
}

// ---------------------------------------------------------------------------
// Kernel 3: column sums of exp'd energies: invS[z][p] = 1/sum_q e'[q][p].
// grid(4, 32), 256 threads; thread owns one p column. Read-only over ebuf.
// ---------------------------------------------------------------------------
__global__ void __launch_bounds__(256) colsum_tc() {
    const int z = blockIdx.y;
    const int p = blockIdx.x * 256 + threadIdx.x;
    const float* e = g_ebuf + (size_t)z * NP * NP + p;
    float s = 0.0f;
    for (int q = 0; q < NP; q += 4) {
        float v0 = e[(size_t)(q + 0) * NP];
        float v1 = e[(size_t)(q + 1) * NP];
        float v2 = e[(size_t)(q + 2) * NP];
        float v3 = e[(size_t)(q + 3) * NP];
        s += (v0 + v1) + (v2 + v3);
    }
    g_sbuf[(size_t)z * NP + p] = 1.0f / s;
}

// ---------------------------------------------------------------------------
// Kernel 4: vt[z][dt][p] = tf32(v[z][p][dt] * invS[p]).  grid(32, 16, 32).
// ---------------------------------------------------------------------------
__global__ void __launch_bounds__(256) vtrans_tc() {
    __shared__ float ts[64][68];
    const int tid = threadIdx.x;
    const int z = blockIdx.z;
    const int dt0 = blockIdx.x * 64;
    const int p0 = blockIdx.y * 64;

    const float* in = g_vbuf + (size_t)z * NP * NDT;
    const float* invS = g_sbuf + (size_t)z * NP;
#pragma unroll
    for (int i = 0; i < 4; ++i) {
        int idx = i * 256 + tid;
        int r = idx >> 4, c4 = (idx & 15) * 4;
        float sc = invS[p0 + r];
        float4 v = *(const float4*)(in + (size_t)(p0 + r) * NDT + dt0 + c4);
        ts[r][c4 + 0] = tf32r(v.x * sc);
        ts[r][c4 + 1] = tf32r(v.y * sc);
        ts[r][c4 + 2] = tf32r(v.z * sc);
        ts[r][c4 + 3] = tf32r(v.w * sc);
    }
    __syncthreads();
    float* out = g_vtbuf + (size_t)z * NDT * NP;
#pragma unroll
    for (int i = 0; i < 4; ++i) {
        int idx = i * 256 + tid;
        int r = idx >> 4, c4 = (idx & 15) * 4;
        float4 w;
        w.x = ts[c4 + 0][r];
        w.y = ts[c4 + 1][r];
        w.z = ts[c4 + 2][r];
        w.w = ts[c4 + 3][r];
        *(float4*)(out + (size_t)(dt0 + r) * NP + p0 + c4) = w;
    }
}

// ---------------------------------------------------------------------------
// Kernel 5: AV. O'[dt][q] = sum_p vt[dt,p] * attn'[q,p]. grid(8, 16, 32).
// Both operands natural (k=p contiguous). Coalesced output (lanes along t).
// ---------------------------------------------------------------------------
__global__ void __launch_bounds__(256, 2) av_tc(float* __restrict__ out) {
    extern __shared__ float sm[];
    const int tid = threadIdx.x, lane = tid & 31, ww = tid >> 5;
    const int z = blockIdx.z, b = z >> 3, h = z & 7;
    const int m0 = blockIdx.y * 128;  // dt
    const int n0 = blockIdx.x * 128;  // q

    float acc[4][4][4];
    run_gemm_nn(sm, g_vtbuf + (size_t)z * NDT * NP + (size_t)m0 * NP, NP,
                g_ebuf + (size_t)z * NP * NP + (size_t)n0 * NP, NP,
                NP / 32, acc);

    const int wmb = (ww >> 2) * 64, wnb = (ww & 3) * 32;
    for (int half = 0; half < 2; ++half) {
        float* Cs = stage_cs_half(sm, acc, half);
        const int dtb = m0 + wmb + half * 32;   // 32 consecutive dt
        const int d = dtb >> 6, tbase = dtb & 63;
        float* ob = out + ((size_t)(b * NC) + h * ND + d) * NP * NT + tbase;
#pragma unroll 4
        for (int nn = 0; nn < 32; ++nn) {
            const int q = n0 + wnb + nn;
            ob[(size_t)q * NT + lane] = Cs[nn * 33 + lane];
        }
    }
}

// ---------------------------------------------------------------------------
extern "C" void kernel_launch(void* const* d_in, const int* in_sizes, int n_in,
                              void* d_out, int out_size) {
    const float* x  = (const float*)d_in[0];
    const float* Wk = (const float*)d_in[1];
    const float* bk = (const float*)d_in[2];
    const float* Wq = (const float*)d_in[3];
    const float* bq = (const float*)d_in[4];
    const float* Wv = (const float*)d_in[5];
    const float* bv = (const float*)d_in[6];
    float* out = (float*)d_out;

    cudaFuncSetAttribute(proj_tc, cudaFuncAttributeMaxDynamicSharedMemorySize, SMEM_GEMM);
    cudaFuncSetAttribute(energy_tc, cudaFuncAttributeMaxDynamicSharedMemorySize, SMEM_GEMM);
    cudaFuncSetAttribute(av_tc, cudaFuncAttributeMaxDynamicSharedMemorySize, SMEM_GEMM);

    wround_tc<<<dim3(64, 3), 256>>>(Wk, Wq, Wv);
    xtrans_tc<<<dim3(NPT / 64, NC / 64, NB), 256>>>(x);
    proj_tc<<<dim3(NPT / 128, 6, NB), 256, SMEM_GEMM>>>(bk, bq, bv);
    energy_tc<<<dim3(NP / 128, NP / 128, NB * NH), 256, SMEM_GEMM>>>();
    colsum_tc<<<dim3(NP / 256, NB * NH), 256>>>();
    vtrans_tc<<<dim3(NDT / 64, NP / 64, NB * NH), 256>>>();
    av_tc<<<dim3(NP / 128, NDT / 128, NB * NH), 256, SMEM_GEMM>>>(out);
}